// round 14
// baseline (speedup 1.0000x reference)
#include <cuda_runtime.h>
#include <math.h>
#include <stdint.h>

// Problem constants
#define BB 8
#define NN 1024
#define CC 512
#define HEADS 8
#define HD 64
#define T_ROWS 3969
#define M_ROWS (BB * NN)      // 8192
#define CPB_HIDDEN 512

// ----------------------------------------------------------------------------
// Scratch (static device globals; no runtime allocation)
// ----------------------------------------------------------------------------
__device__ float g_qkv[(size_t)M_ROWS * 3 * CC];
__device__ float g_q[(size_t)BB * HEADS * NN * HD];
__device__ float g_k[(size_t)BB * HEADS * NN * HD];
__device__ float g_v[(size_t)BB * HEADS * NN * HD];
__device__ float g_bias[T_ROWS * HEADS];
__device__ float g_biasmat[(size_t)HEADS * NN * NN];
// tf32 split buffers for GEMMs
__device__ float g_ahi[(size_t)M_ROWS * CC];
__device__ float g_alo[(size_t)M_ROWS * CC];
__device__ float g_whi[(size_t)3 * CC * CC];
__device__ float g_wlo[(size_t)3 * CC * CC];
__device__ float g_pwhi[(size_t)CC * CC];
__device__ float g_pwlo[(size_t)CC * CC];

// ----------------------------------------------------------------------------
// tf32 / async helpers
// ----------------------------------------------------------------------------
__device__ __forceinline__ float tf32_rna(float v) {
    uint32_t r;
    asm("cvt.rna.tf32.f32 %0, %1;" : "=r"(r) : "f"(v));
    return __uint_as_float(r);
}

__device__ __forceinline__ void mma_tf32(float* d, uint32_t a0, uint32_t a1,
                                         uint32_t a2, uint32_t a3,
                                         uint32_t b0, uint32_t b1) {
    asm volatile(
        "mma.sync.aligned.m16n8k8.row.col.f32.tf32.tf32.f32 "
        "{%0,%1,%2,%3}, {%4,%5,%6,%7}, {%8,%9}, {%0,%1,%2,%3};"
        : "+f"(d[0]), "+f"(d[1]), "+f"(d[2]), "+f"(d[3])
        : "r"(a0), "r"(a1), "r"(a2), "r"(a3), "r"(b0), "r"(b1));
}

__device__ __forceinline__ void split2(float v, uint32_t& hi, uint32_t& lo) {
    float h = tf32_rna(v);
    hi = __float_as_uint(h);
    lo = __float_as_uint(v - h);
}

__device__ __forceinline__ void cp16(uint32_t saddr, const void* g) {
    asm volatile("cp.async.ca.shared.global [%0], [%1], 16;"
                 :: "r"(saddr), "l"(g));
}
#define CP_COMMIT() asm volatile("cp.async.commit_group;" ::: "memory")
#define CP_WAIT0()  asm volatile("cp.async.wait_group 0;" ::: "memory")
#define CP_WAIT1()  asm volatile("cp.async.wait_group 1;" ::: "memory")

// ----------------------------------------------------------------------------
// Split a float array into tf32 hi/lo parts
// ----------------------------------------------------------------------------
__global__ __launch_bounds__(256) void split_kernel(
    const float* __restrict__ src, float* __restrict__ hi,
    float* __restrict__ lo, int n4)
{
    int i = blockIdx.x * 256 + threadIdx.x;
    if (i >= n4) return;
    float4 v = *(const float4*)(src + i * 4);
    float4 h, l;
    h.x = tf32_rna(v.x); l.x = v.x - h.x;
    h.y = tf32_rna(v.y); l.y = v.y - h.y;
    h.z = tf32_rna(v.z); l.z = v.z - h.z;
    h.w = tf32_rna(v.w); l.w = v.w - h.w;
    *(float4*)(hi + i * 4) = h;
    *(float4*)(lo + i * 4) = l;
}

// ----------------------------------------------------------------------------
// tf32 mma GEMM (3x split), cp.async 3-stage pipelined.
// ----------------------------------------------------------------------------
#define GP 36
#define GEMM_STAGE (4 * 128 * GP)
#define GEMM_SMEM (3 * GEMM_STAGE * 4)

__global__ __launch_bounds__(256, 1)
void mma_gemm_kernel(const float* __restrict__ Ahi, const float* __restrict__ Alo,
                     const float* __restrict__ Bhi, const float* __restrict__ Blo,
                     const float* __restrict__ bias, float* __restrict__ C, int Nn)
{
    extern __shared__ float sm[];

    int tid = threadIdx.x;
    int wid = tid >> 5, lane = tid & 31;
    int g = lane >> 2, t = lane & 3;
    int wm = (wid & 3) * 32;
    int wn = (wid >> 2) * 64;
    int m0 = blockIdx.y * 128, n0 = blockIdx.x * 128;

    int sm_m[4], sm_k4[4];
    size_t ga[4], gb[4];
#pragma unroll
    for (int it = 0; it < 4; it++) {
        int idx = tid + it * 256;
        sm_m[it] = idx >> 3;
        sm_k4[it] = (idx & 7) << 2;
        ga[it] = (size_t)(m0 + sm_m[it]) * 512 + sm_k4[it];
        gb[it] = (size_t)(n0 + sm_m[it]) * 512 + sm_k4[it];
    }

    uint32_t sbase = (uint32_t)__cvta_generic_to_shared(sm);

    auto issue = [&](int ch, int buf) {
        uint32_t st = sbase + (uint32_t)buf * GEMM_STAGE * 4;
#pragma unroll
        for (int it = 0; it < 4; it++) {
            uint32_t off = (uint32_t)(sm_m[it] * GP + sm_k4[it]) * 4;
            size_t go = ga[it] + ch * 32;
            size_t bo = gb[it] + ch * 32;
            cp16(st + off,                      Ahi + go);
            cp16(st + 128 * GP * 4 + off,       Alo + go);
            cp16(st + 2 * 128 * GP * 4 + off,   Bhi + bo);
            cp16(st + 3 * 128 * GP * 4 + off,   Blo + bo);
        }
        CP_COMMIT();
    };

    float d[2][8][4];
#pragma unroll
    for (int mt = 0; mt < 2; mt++)
#pragma unroll
        for (int nt = 0; nt < 8; nt++)
#pragma unroll
            for (int r = 0; r < 4; r++) d[mt][nt][r] = 0.f;

    issue(0, 0);
    issue(1, 1);

    int buf = 0;
    for (int ch = 0; ch < 16; ch++) {
        CP_WAIT1();
        __syncthreads();
        if (ch < 14) issue(ch + 2, (buf + 2) % 3);

        float* st = sm + buf * GEMM_STAGE;
        float* sAh = st;
        float* sAl = st + 128 * GP;
        float* sBh = st + 2 * 128 * GP;
        float* sBl = st + 3 * 128 * GP;

#pragma unroll
        for (int ks = 0; ks < 4; ks++) {
            uint32_t ah[2][4], al[2][4];
#pragma unroll
            for (int mt = 0; mt < 2; mt++) {
                const float* p = sAh + (wm + mt * 16 + g) * GP + ks * 8 + t;
                const float* q = sAl + (wm + mt * 16 + g) * GP + ks * 8 + t;
                ah[mt][0] = __float_as_uint(p[0]);
                ah[mt][1] = __float_as_uint(p[8 * GP]);
                ah[mt][2] = __float_as_uint(p[4]);
                ah[mt][3] = __float_as_uint(p[8 * GP + 4]);
                al[mt][0] = __float_as_uint(q[0]);
                al[mt][1] = __float_as_uint(q[8 * GP]);
                al[mt][2] = __float_as_uint(q[4]);
                al[mt][3] = __float_as_uint(q[8 * GP + 4]);
            }
            uint32_t bh[8][2], bl[8][2];
#pragma unroll
            for (int nt = 0; nt < 8; nt++) {
                const float* p = sBh + (wn + nt * 8 + g) * GP + ks * 8 + t;
                const float* q = sBl + (wn + nt * 8 + g) * GP + ks * 8 + t;
                bh[nt][0] = __float_as_uint(p[0]);
                bh[nt][1] = __float_as_uint(p[4]);
                bl[nt][0] = __float_as_uint(q[0]);
                bl[nt][1] = __float_as_uint(q[4]);
            }
#pragma unroll
            for (int mt = 0; mt < 2; mt++)
#pragma unroll
                for (int nt = 0; nt < 8; nt++) {
                    mma_tf32(d[mt][nt], ah[mt][0], ah[mt][1], ah[mt][2], ah[mt][3],
                             bh[nt][0], bh[nt][1]);
                    mma_tf32(d[mt][nt], ah[mt][0], ah[mt][1], ah[mt][2], ah[mt][3],
                             bl[nt][0], bl[nt][1]);
                    mma_tf32(d[mt][nt], al[mt][0], al[mt][1], al[mt][2], al[mt][3],
                             bh[nt][0], bh[nt][1]);
                }
        }
        __syncthreads();
        buf = (buf + 1) % 3;
    }

#pragma unroll
    for (int nt = 0; nt < 8; nt++) {
        int col = n0 + wn + nt * 8 + 2 * t;
        float b0 = bias[col], b1 = bias[col + 1];
#pragma unroll
        for (int mt = 0; mt < 2; mt++) {
            int row = m0 + wm + mt * 16 + g;
            float2 v0 = make_float2(d[mt][nt][0] + b0, d[mt][nt][1] + b1);
            float2 v1 = make_float2(d[mt][nt][2] + b0, d[mt][nt][3] + b1);
            *(float2*)(C + (size_t)row * Nn + col) = v0;
            *(float2*)(C + (size_t)(row + 8) * Nn + col) = v1;
        }
    }
}

// ----------------------------------------------------------------------------
// CPB MLP
// ----------------------------------------------------------------------------
__global__ __launch_bounds__(512) void cpb_kernel(
    const float* __restrict__ table,
    const float* __restrict__ fc1w, const float* __restrict__ fc1b,
    const float* __restrict__ fc2w, const float* __restrict__ fc2b)
{
    __shared__ float sh[CPB_HIDDEN];
    __shared__ float part[16];
    int t = blockIdx.x;
    int tid = threadIdx.x;

    float c0 = table[t * 2 + 0];
    float c1 = table[t * 2 + 1];
    float hv = c0 * fc1w[tid * 2 + 0] + c1 * fc1w[tid * 2 + 1] + fc1b[tid];
    sh[tid] = fmaxf(hv, 0.f);
    __syncthreads();

    int w = tid >> 5, lane = tid & 31;
    int head = w & 7, seg = w >> 3;
    float s = 0.f;
#pragma unroll
    for (int i = 0; i < 8; i++) {
        int j = seg * 256 + i * 32 + lane;
        s += sh[j] * fc2w[head * CPB_HIDDEN + j];
    }
#pragma unroll
    for (int off = 16; off; off >>= 1)
        s += __shfl_xor_sync(0xffffffffu, s, off);
    if (lane == 0) part[w] = s;
    __syncthreads();
    if (tid < 8) g_bias[t * 8 + tid] = part[tid] + part[tid + 8] + fc2b[tid];
}

// ----------------------------------------------------------------------------
// Materialize bias matrix
// ----------------------------------------------------------------------------
__global__ __launch_bounds__(256) void bias_mat_kernel(const int* __restrict__ relidx)
{
    int gid = blockIdx.x * 256 + threadIdx.x;
    int m4 = gid & 255;
    int n  = (gid >> 8) & 1023;
    int h  = gid >> 18;
    int4 idx = *(const int4*)(relidx + (size_t)n * NN + m4 * 4);
    float4 o;
    o.x = g_bias[idx.x * 8 + h];
    o.y = g_bias[idx.y * 8 + h];
    o.z = g_bias[idx.z * 8 + h];
    o.w = g_bias[idx.w * 8 + h];
    *(float4*)(g_biasmat + ((size_t)h * NN + n) * NN + m4 * 4) = o;
}

// ----------------------------------------------------------------------------
// Prep: split qkv per-(b,h); L2-normalize q,k; scale q. (fp32 outputs)
// ----------------------------------------------------------------------------
__global__ __launch_bounds__(256) void prep_kernel(
    const float* __restrict__ temperature,
    const float* __restrict__ query_emb,
    const float* __restrict__ seq_scale)
{
    int gid = blockIdx.x * 8 + (threadIdx.x >> 5);
    int lane = threadIdx.x & 31;
    int m = gid >> 3, h = gid & 7;
    int b = m >> 10, n = m & 1023;

    const float* src = g_qkv + (size_t)m * (3 * CC) + h * HD;
    float q0 = src[lane],           q1 = src[lane + 32];
    float k0 = src[CC + lane],      k1 = src[CC + lane + 32];
    float v0 = src[2 * CC + lane],  v1 = src[2 * CC + lane + 32];

    float sq = q0 * q0 + q1 * q1;
    float sk = k0 * k0 + k1 * k1;
#pragma unroll
    for (int off = 16; off; off >>= 1) {
        sq += __shfl_xor_sync(0xffffffffu, sq, off);
        sk += __shfl_xor_sync(0xffffffffu, sk, off);
    }
    float qinv = 1.f / fmaxf(sqrtf(sq), 1e-12f);
    float kinv = 1.f / fmaxf(sqrtf(sk), 1e-12f);

    float tv = temperature[h];
    float sp = (tv > 20.f) ? tv : log1pf(expf(tv));
    float scale = sp * seq_scale[0];

    size_t dst = ((size_t)(b * 8 + h) * NN + n) * HD;
    g_q[dst + lane]      = (q0 * qinv + query_emb[h * HD + lane]) * scale;
    g_q[dst + lane + 32] = (q1 * qinv + query_emb[h * HD + lane + 32]) * scale;
    g_k[dst + lane]      = k0 * kinv;
    g_k[dst + lane + 32] = k1 * kinv;
    g_v[dst + lane]      = v0;
    g_v[dst + lane + 32] = v1;
}

// ----------------------------------------------------------------------------
// Flash attention, tf32 mma, 128q x 128k tile, 256 threads (8 warps).
// cp.async pipeline: raw K/V tile kt+1 streams into sRaw during compute of kt
// (single raw buffer; split phase drains it before the next issue).
// Q staged once through sRaw: Q-hi -> smem, Q-lo a-frags -> registers.
// V hi-only PV (2-term); in-register c->a fragment transpose.
// smem: Qh/Kh/Kl 128x68, Vh 128x72, raw 128x128 = 206848 B.
// ----------------------------------------------------------------------------
#define QP 68
#define VP 72
#define RAW_F (128 * 64)      // floats per raw array (K or V)
#define ATTN_SMEM ((3 * 128 * QP + 128 * VP + 2 * RAW_F) * 4)

__global__ __launch_bounds__(256, 1) void attn_kernel()
{
    extern __shared__ float sm[];
    float* sQh  = sm;
    float* sKh  = sQh + 128 * QP;
    float* sKl  = sKh + 128 * QP;
    float* sVh  = sKl + 128 * QP;
    float* sRaw = sVh + 128 * VP;            // K raw [0,RAW_F), V raw [RAW_F,2*RAW_F)

    int bh = blockIdx.x;          // 0..63
    int qt = blockIdx.y;          // 0..7
    int h = bh & 7, b = bh >> 3;
    int tid = threadIdx.x;
    int wid = tid >> 5, lane = tid & 31;
    int g = lane >> 2, t = lane & 3;
    int q0g = qt * 128;
    int wrow = wid * 16;
    int sel = t & 1;
    int src0 = (lane & 28) | (t >> 1);
    int src2 = src0 + 2;

    uint32_t rawb = (uint32_t)__cvta_generic_to_shared(sRaw);

    // per-thread staging coords (8 float4 per array)
    int st_row[8], st_c4[8];
#pragma unroll
    for (int it = 0; it < 8; it++) {
        int i = tid + it * 256;
        st_row[it] = i >> 4;
        st_c4[it] = (i & 15) << 2;
    }

    // ---- prologue: stage Q raw, extract Q-hi smem + Q-lo frags in regs ----
    const float* Qg = g_q + ((size_t)bh * NN + q0g) * HD;
#pragma unroll
    for (int it = 0; it < 8; it++)
        cp16(rawb + (uint32_t)(st_row[it] * 64 + st_c4[it]) * 4,
             Qg + st_row[it] * HD + st_c4[it]);
    CP_COMMIT();
    CP_WAIT0();
    __syncthreads();

    uint32_t alr[8][4];   // Q-lo a-frags (registers)
#pragma unroll
    for (int ks = 0; ks < 8; ks++) {
        float a0 = sRaw[(wrow + g) * 64 + ks * 8 + t];
        float a1 = sRaw[(wrow + g + 8) * 64 + ks * 8 + t];
        float a2 = sRaw[(wrow + g) * 64 + ks * 8 + t + 4];
        float a3 = sRaw[(wrow + g + 8) * 64 + ks * 8 + t + 4];
        alr[ks][0] = __float_as_uint(a0 - tf32_rna(a0));
        alr[ks][1] = __float_as_uint(a1 - tf32_rna(a1));
        alr[ks][2] = __float_as_uint(a2 - tf32_rna(a2));
        alr[ks][3] = __float_as_uint(a3 - tf32_rna(a3));
    }
#pragma unroll
    for (int it = 0; it < 8; it++) {
        float4 v = *(const float4*)(sRaw + st_row[it] * 64 + st_c4[it]);
        float4 hh;
        hh.x = tf32_rna(v.x); hh.y = tf32_rna(v.y);
        hh.z = tf32_rna(v.z); hh.w = tf32_rna(v.w);
        *(float4*)(sQh + st_row[it] * QP + st_c4[it]) = hh;
    }
    __syncthreads();   // raw buffer free

    // issue raw K/V for tile 0
    const float* Kgb = g_k + (size_t)bh * NN * HD;
    const float* Vgb = g_v + (size_t)bh * NN * HD;
#pragma unroll
    for (int it = 0; it < 8; it++) {
        uint32_t off = (uint32_t)(st_row[it] * 64 + st_c4[it]) * 4;
        cp16(rawb + off,              Kgb + st_row[it] * HD + st_c4[it]);
        cp16(rawb + RAW_F * 4 + off,  Vgb + st_row[it] * HD + st_c4[it]);
    }
    CP_COMMIT();

    float o[8][4];
#pragma unroll
    for (int nt = 0; nt < 8; nt++)
#pragma unroll
        for (int r = 0; r < 4; r++) o[nt][r] = 0.f;
    float mrow0 = -1e30f, mrow1 = -1e30f, lrow0 = 0.f, lrow1 = 0.f;

    const float* bmat = g_biasmat + ((size_t)h * NN + q0g) * NN;

    for (int kt = 0; kt < 8; kt++) {
        CP_WAIT0();
        __syncthreads();   // raw tile ready; prior compute done with sKh/sKl/sVh

        // ---- split raw -> Kh/Kl/Vh ----
#pragma unroll
        for (int it = 0; it < 8; it++) {
            int row = st_row[it], c4 = st_c4[it];
            float4 kv = *(const float4*)(sRaw + row * 64 + c4);
            float4 vv = *(const float4*)(sRaw + RAW_F + row * 64 + c4);
            float4 hh, ll;
            hh.x = tf32_rna(kv.x); ll.x = kv.x - hh.x;
            hh.y = tf32_rna(kv.y); ll.y = kv.y - hh.y;
            hh.z = tf32_rna(kv.z); ll.z = kv.z - hh.z;
            hh.w = tf32_rna(kv.w); ll.w = kv.w - hh.w;
            *(float4*)(sKh + row * QP + c4) = hh;
            *(float4*)(sKl + row * QP + c4) = ll;
            float4 vh;
            vh.x = tf32_rna(vv.x); vh.y = tf32_rna(vv.y);
            vh.z = tf32_rna(vv.z); vh.w = tf32_rna(vv.w);
            *(float4*)(sVh + row * VP + c4) = vh;
        }
        __syncthreads();   // raw buffer drained; splits visible

        // prefetch next tile's raw K/V (overlaps compute below)
        if (kt < 7) {
            const float* Kg = Kgb + (size_t)(kt + 1) * 128 * HD;
            const float* Vg = Vgb + (size_t)(kt + 1) * 128 * HD;
#pragma unroll
            for (int it = 0; it < 8; it++) {
                uint32_t off = (uint32_t)(st_row[it] * 64 + st_c4[it]) * 4;
                cp16(rawb + off,              Kg + st_row[it] * HD + st_c4[it]);
                cp16(rawb + RAW_F * 4 + off,  Vg + st_row[it] * HD + st_c4[it]);
            }
            CP_COMMIT();
        }

        // ---- QK^T: c[16][4] over all 128 keys ----
        float c[16][4];
#pragma unroll
        for (int nt = 0; nt < 16; nt++)
#pragma unroll
            for (int r = 0; r < 4; r++) c[nt][r] = 0.f;

#pragma unroll
        for (int ks = 0; ks < 8; ks++) {
            const float* ph = sQh + (wrow + g) * QP + ks * 8 + t;
            uint32_t ah0 = __float_as_uint(ph[0]);
            uint32_t ah1 = __float_as_uint(ph[8 * QP]);
            uint32_t ah2 = __float_as_uint(ph[4]);
            uint32_t ah3 = __float_as_uint(ph[8 * QP + 4]);
#pragma unroll
            for (int nt = 0; nt < 16; nt++) {
                const float* kh = sKh + (nt * 8 + g) * QP + ks * 8 + t;
                const float* kl = sKl + (nt * 8 + g) * QP + ks * 8 + t;
                uint32_t bh0 = __float_as_uint(kh[0]);
                uint32_t bh1 = __float_as_uint(kh[4]);
                uint32_t bl0 = __float_as_uint(kl[0]);
                uint32_t bl1 = __float_as_uint(kl[4]);
                mma_tf32(c[nt], ah0, ah1, ah2, ah3, bh0, bh1);
                mma_tf32(c[nt], ah0, ah1, ah2, ah3, bl0, bl1);
                mma_tf32(c[nt], alr[ks][0], alr[ks][1], alr[ks][2], alr[ks][3],
                         bh0, bh1);
            }
        }

        // ---- bias add ----
#pragma unroll
        for (int nt = 0; nt < 16; nt++) {
            const float* bp = bmat + (size_t)(wrow + g) * NN + kt * 128 + nt * 8 + 2 * t;
            float2 b0 = *(const float2*)bp;
            float2 b1 = *(const float2*)(bp + (size_t)8 * NN);
            c[nt][0] += b0.x; c[nt][1] += b0.y;
            c[nt][2] += b1.x; c[nt][3] += b1.y;
        }

        // ---- online softmax (rows g and g+8, in-warp quad reductions) ----
        float mt0 = -1e30f, mt1 = -1e30f;
#pragma unroll
        for (int nt = 0; nt < 16; nt++) {
            mt0 = fmaxf(mt0, fmaxf(c[nt][0], c[nt][1]));
            mt1 = fmaxf(mt1, fmaxf(c[nt][2], c[nt][3]));
        }
        mt0 = fmaxf(mt0, __shfl_xor_sync(0xffffffffu, mt0, 1));
        mt0 = fmaxf(mt0, __shfl_xor_sync(0xffffffffu, mt0, 2));
        mt1 = fmaxf(mt1, __shfl_xor_sync(0xffffffffu, mt1, 1));
        mt1 = fmaxf(mt1, __shfl_xor_sync(0xffffffffu, mt1, 2));

        float nm0 = fmaxf(mrow0, mt0), nm1 = fmaxf(mrow1, mt1);
        float corr0 = __expf(mrow0 - nm0), corr1 = __expf(mrow1 - nm1);
        mrow0 = nm0; mrow1 = nm1;

        float ps0 = 0.f, ps1 = 0.f;
#pragma unroll
        for (int nt = 0; nt < 16; nt++) {
            c[nt][0] = __expf(c[nt][0] - nm0); ps0 += c[nt][0];
            c[nt][1] = __expf(c[nt][1] - nm0); ps0 += c[nt][1];
            c[nt][2] = __expf(c[nt][2] - nm1); ps1 += c[nt][2];
            c[nt][3] = __expf(c[nt][3] - nm1); ps1 += c[nt][3];
        }
        ps0 += __shfl_xor_sync(0xffffffffu, ps0, 1);
        ps0 += __shfl_xor_sync(0xffffffffu, ps0, 2);
        ps1 += __shfl_xor_sync(0xffffffffu, ps1, 1);
        ps1 += __shfl_xor_sync(0xffffffffu, ps1, 2);
        lrow0 = lrow0 * corr0 + ps0;
        lrow1 = lrow1 * corr1 + ps1;

#pragma unroll
        for (int nt = 0; nt < 8; nt++) {
            o[nt][0] *= corr0; o[nt][1] *= corr0;
            o[nt][2] *= corr1; o[nt][3] *= corr1;
        }

        // ---- PV: c-frag -> a-frag via quad shuffles; split P; V hi-only ----
#pragma unroll
        for (int kk = 0; kk < 16; kk++) {
            float y00 = __shfl_sync(0xffffffffu, c[kk][0], src0);
            float y01 = __shfl_sync(0xffffffffu, c[kk][1], src0);
            float y20 = __shfl_sync(0xffffffffu, c[kk][0], src2);
            float y21 = __shfl_sync(0xffffffffu, c[kk][1], src2);
            float y10 = __shfl_sync(0xffffffffu, c[kk][2], src0);
            float y11 = __shfl_sync(0xffffffffu, c[kk][3], src0);
            float y30 = __shfl_sync(0xffffffffu, c[kk][2], src2);
            float y31 = __shfl_sync(0xffffffffu, c[kk][3], src2);
            float p0 = sel ? y01 : y00;
            float p1 = sel ? y11 : y10;
            float p2 = sel ? y21 : y20;
            float p3 = sel ? y31 : y30;
            uint32_t ph0, ph1, ph2, ph3, pl0, pl1, pl2, pl3;
            split2(p0, ph0, pl0); split2(p1, ph1, pl1);
            split2(p2, ph2, pl2); split2(p3, ph3, pl3);
#pragma unroll
            for (int nt = 0; nt < 8; nt++) {
                const float* vh = sVh + (kk * 8 + t) * VP + nt * 8 + g;
                uint32_t vh0 = __float_as_uint(vh[0]);
                uint32_t vh1 = __float_as_uint(vh[4 * VP]);
                mma_tf32(o[nt], ph0, ph1, ph2, ph3, vh0, vh1);
                mma_tf32(o[nt], pl0, pl1, pl2, pl3, vh0, vh1);
            }
        }
    }

    // ---- epilogue: normalize, fused tf32 split of proj input ----
    float inv0 = 1.f / lrow0, inv1 = 1.f / lrow1;
    int rowA = q0g + wrow + g;
#pragma unroll
    for (int nt = 0; nt < 8; nt++) {
        float v0 = o[nt][0] * inv0, v1 = o[nt][1] * inv0;
        float v2 = o[nt][2] * inv1, v3 = o[nt][3] * inv1;
        float h0 = tf32_rna(v0), h1 = tf32_rna(v1);
        float h2 = tf32_rna(v2), h3 = tf32_rna(v3);
        size_t pA = ((size_t)b * NN + rowA) * CC + h * HD + nt * 8 + 2 * t;
        size_t pB = ((size_t)b * NN + rowA + 8) * CC + h * HD + nt * 8 + 2 * t;
        *(float2*)(g_ahi + pA) = make_float2(h0, h1);
        *(float2*)(g_alo + pA) = make_float2(v0 - h0, v1 - h1);
        *(float2*)(g_ahi + pB) = make_float2(h2, h3);
        *(float2*)(g_alo + pB) = make_float2(v2 - h2, v3 - h3);
    }
}

// ----------------------------------------------------------------------------
// launch
// ----------------------------------------------------------------------------
extern "C" void kernel_launch(void* const* d_in, const int* in_sizes, int n_in,
                              void* d_out, int out_size)
{
    int ri = 1;
    while (ri < n_in && in_sizes[ri] != NN * NN) ri++;

    const float* x        = (const float*)d_in[0];
    const int*   relidx   = (const int*)d_in[ri];
    const float* table    = (const float*)d_in[ri + 1];
    const float* seqscale = (const float*)d_in[ri + 2];
    const float* qkv_w    = (const float*)d_in[ri + 3];
    const float* qkv_b    = (const float*)d_in[ri + 4];
    const float* proj_w   = (const float*)d_in[ri + 5];
    const float* proj_b   = (const float*)d_in[ri + 6];
    const float* temp     = (const float*)d_in[ri + 7];
    const float* qemb     = (const float*)d_in[ri + 8];
    const float* fc1w     = (const float*)d_in[ri + 9];
    const float* fc1b     = (const float*)d_in[ri + 10];
    const float* fc2w     = (const float*)d_in[ri + 11];
    const float* fc2b     = (const float*)d_in[ri + 12];
    float* out = (float*)d_out;

    float *qkvbuf, *ahi, *alo, *whi, *wlo, *pwhi, *pwlo;
    cudaGetSymbolAddress((void**)&qkvbuf, g_qkv);
    cudaGetSymbolAddress((void**)&ahi, g_ahi);
    cudaGetSymbolAddress((void**)&alo, g_alo);
    cudaGetSymbolAddress((void**)&whi, g_whi);
    cudaGetSymbolAddress((void**)&wlo, g_wlo);
    cudaGetSymbolAddress((void**)&pwhi, g_pwhi);
    cudaGetSymbolAddress((void**)&pwlo, g_pwlo);

    cudaFuncSetAttribute(mma_gemm_kernel,
                         cudaFuncAttributeMaxDynamicSharedMemorySize, GEMM_SMEM);

    // 1) QKV projection (tf32 mma, 3x split, cp.async 3-stage pipeline)
    split_kernel<<<(M_ROWS * CC / 4 + 255) / 256, 256>>>(x, ahi, alo, M_ROWS * CC / 4);
    split_kernel<<<(3 * CC * CC / 4 + 255) / 256, 256>>>(qkv_w, whi, wlo, 3 * CC * CC / 4);
    {
        dim3 grid(3 * CC / 128, M_ROWS / 128);
        mma_gemm_kernel<<<grid, 256, GEMM_SMEM>>>(ahi, alo, whi, wlo,
                                                  qkv_b, qkvbuf, 3 * CC);
    }

    // 2) CPB MLP -> bias table, then materialize full bias matrix
    cpb_kernel<<<T_ROWS, 512>>>(table, fc1w, fc1b, fc2w, fc2b);
    bias_mat_kernel<<<HEADS * NN * (NN / 4) / 256, 256>>>(relidx);

    // 3) normalize/scale, re-layout (fp32); proj weight split (independent)
    prep_kernel<<<M_ROWS * HEADS / 8, 256>>>(temp, qemb, seqscale);
    split_kernel<<<(CC * CC / 4 + 255) / 256, 256>>>(proj_w, pwhi, pwlo, CC * CC / 4);

    // 4) flash attention (tf32 mma, cp.async-prefetched raw K/V)
    {
        cudaFuncSetAttribute(attn_kernel,
                             cudaFuncAttributeMaxDynamicSharedMemorySize,
                             ATTN_SMEM);
        dim3 grid(BB * HEADS, NN / 128);
        attn_kernel<<<grid, 256, ATTN_SMEM>>>();
    }

    // 5) output projection (tf32 mma; input split fused into attn epilogue)
    {
        dim3 grid(CC / 128, M_ROWS / 128);
        mma_gemm_kernel<<<grid, 256, GEMM_SMEM>>>(ahi, alo, pwhi, pwlo,
                                                  proj_b, out, CC);
    }
}

// round 15
// speedup vs baseline: 1.0598x; 1.0598x over previous
#include <cuda_runtime.h>
#include <math.h>
#include <stdint.h>

// Problem constants
#define BB 8
#define NN 1024
#define CC 512
#define HEADS 8
#define HD 64
#define T_ROWS 3969
#define M_ROWS (BB * NN)      // 8192
#define CPB_HIDDEN 512

// ----------------------------------------------------------------------------
// Scratch (static device globals; no runtime allocation)
// ----------------------------------------------------------------------------
__device__ float g_qkv[(size_t)M_ROWS * 3 * CC];
__device__ float g_q[(size_t)BB * HEADS * NN * HD];
__device__ float g_k[(size_t)BB * HEADS * NN * HD];
__device__ float g_v[(size_t)BB * HEADS * NN * HD];
__device__ float g_bias[T_ROWS * HEADS];
__device__ float g_biasmat[(size_t)HEADS * NN * NN];
// tf32 split buffers for GEMMs
__device__ float g_ahi[(size_t)M_ROWS * CC];
__device__ float g_alo[(size_t)M_ROWS * CC];
__device__ float g_whi[(size_t)3 * CC * CC];
__device__ float g_wlo[(size_t)3 * CC * CC];
__device__ float g_pwhi[(size_t)CC * CC];
__device__ float g_pwlo[(size_t)CC * CC];

// ----------------------------------------------------------------------------
// tf32 / async helpers
// ----------------------------------------------------------------------------
__device__ __forceinline__ float tf32_rna(float v) {
    uint32_t r;
    asm("cvt.rna.tf32.f32 %0, %1;" : "=r"(r) : "f"(v));
    return __uint_as_float(r);
}

__device__ __forceinline__ void mma_tf32(float* d, uint32_t a0, uint32_t a1,
                                         uint32_t a2, uint32_t a3,
                                         uint32_t b0, uint32_t b1) {
    asm volatile(
        "mma.sync.aligned.m16n8k8.row.col.f32.tf32.tf32.f32 "
        "{%0,%1,%2,%3}, {%4,%5,%6,%7}, {%8,%9}, {%0,%1,%2,%3};"
        : "+f"(d[0]), "+f"(d[1]), "+f"(d[2]), "+f"(d[3])
        : "r"(a0), "r"(a1), "r"(a2), "r"(a3), "r"(b0), "r"(b1));
}

__device__ __forceinline__ void split2(float v, uint32_t& hi, uint32_t& lo) {
    float h = tf32_rna(v);
    hi = __float_as_uint(h);
    lo = __float_as_uint(v - h);
}

__device__ __forceinline__ void cp16(uint32_t saddr, const void* g) {
    asm volatile("cp.async.ca.shared.global [%0], [%1], 16;"
                 :: "r"(saddr), "l"(g));
}
#define CP_COMMIT() asm volatile("cp.async.commit_group;" ::: "memory")
#define CP_WAIT1()  asm volatile("cp.async.wait_group 1;" ::: "memory")

// ----------------------------------------------------------------------------
// Split a float array into tf32 hi/lo parts
// ----------------------------------------------------------------------------
__global__ __launch_bounds__(256) void split_kernel(
    const float* __restrict__ src, float* __restrict__ hi,
    float* __restrict__ lo, int n4)
{
    int i = blockIdx.x * 256 + threadIdx.x;
    if (i >= n4) return;
    float4 v = *(const float4*)(src + i * 4);
    float4 h, l;
    h.x = tf32_rna(v.x); l.x = v.x - h.x;
    h.y = tf32_rna(v.y); l.y = v.y - h.y;
    h.z = tf32_rna(v.z); l.z = v.z - h.z;
    h.w = tf32_rna(v.w); l.w = v.w - h.w;
    *(float4*)(hi + i * 4) = h;
    *(float4*)(lo + i * 4) = l;
}

// ----------------------------------------------------------------------------
// tf32 mma GEMM (3x split), cp.async 3-stage pipelined.
// C[M,Nn] = A[M,512] @ W[Nn,512]^T + bias[Nn]. CTA 128x128, BK=32.
// ----------------------------------------------------------------------------
#define GP 36
#define GEMM_STAGE (4 * 128 * GP)          // floats per stage
#define GEMM_SMEM (3 * GEMM_STAGE * 4)     // 221184 B

__global__ __launch_bounds__(256, 1)
void mma_gemm_kernel(const float* __restrict__ Ahi, const float* __restrict__ Alo,
                     const float* __restrict__ Bhi, const float* __restrict__ Blo,
                     const float* __restrict__ bias, float* __restrict__ C, int Nn)
{
    extern __shared__ float sm[];

    int tid = threadIdx.x;
    int wid = tid >> 5, lane = tid & 31;
    int g = lane >> 2, t = lane & 3;
    int wm = (wid & 3) * 32;
    int wn = (wid >> 2) * 64;
    int m0 = blockIdx.y * 128, n0 = blockIdx.x * 128;

    int sm_m[4], sm_k4[4];
    size_t ga[4], gb[4];
#pragma unroll
    for (int it = 0; it < 4; it++) {
        int idx = tid + it * 256;
        sm_m[it] = idx >> 3;
        sm_k4[it] = (idx & 7) << 2;
        ga[it] = (size_t)(m0 + sm_m[it]) * 512 + sm_k4[it];
        gb[it] = (size_t)(n0 + sm_m[it]) * 512 + sm_k4[it];
    }

    uint32_t sbase = (uint32_t)__cvta_generic_to_shared(sm);

    auto issue = [&](int ch, int buf) {
        uint32_t st = sbase + (uint32_t)buf * GEMM_STAGE * 4;
#pragma unroll
        for (int it = 0; it < 4; it++) {
            uint32_t off = (uint32_t)(sm_m[it] * GP + sm_k4[it]) * 4;
            size_t go = ga[it] + ch * 32;
            size_t bo = gb[it] + ch * 32;
            cp16(st + off,                      Ahi + go);
            cp16(st + 128 * GP * 4 + off,       Alo + go);
            cp16(st + 2 * 128 * GP * 4 + off,   Bhi + bo);
            cp16(st + 3 * 128 * GP * 4 + off,   Blo + bo);
        }
        CP_COMMIT();
    };

    float d[2][8][4];
#pragma unroll
    for (int mt = 0; mt < 2; mt++)
#pragma unroll
        for (int nt = 0; nt < 8; nt++)
#pragma unroll
            for (int r = 0; r < 4; r++) d[mt][nt][r] = 0.f;

    issue(0, 0);
    issue(1, 1);

    int buf = 0;
    for (int ch = 0; ch < 16; ch++) {
        CP_WAIT1();                 // chunk ch's group complete (<=1 pending)
        __syncthreads();            // all staging visible; prior reads of buf done
        if (ch < 14) issue(ch + 2, (buf + 2) % 3);

        float* st = sm + buf * GEMM_STAGE;
        float* sAh = st;
        float* sAl = st + 128 * GP;
        float* sBh = st + 2 * 128 * GP;
        float* sBl = st + 3 * 128 * GP;

#pragma unroll
        for (int ks = 0; ks < 4; ks++) {
            uint32_t ah[2][4], al[2][4];
#pragma unroll
            for (int mt = 0; mt < 2; mt++) {
                const float* p = sAh + (wm + mt * 16 + g) * GP + ks * 8 + t;
                const float* q = sAl + (wm + mt * 16 + g) * GP + ks * 8 + t;
                ah[mt][0] = __float_as_uint(p[0]);
                ah[mt][1] = __float_as_uint(p[8 * GP]);
                ah[mt][2] = __float_as_uint(p[4]);
                ah[mt][3] = __float_as_uint(p[8 * GP + 4]);
                al[mt][0] = __float_as_uint(q[0]);
                al[mt][1] = __float_as_uint(q[8 * GP]);
                al[mt][2] = __float_as_uint(q[4]);
                al[mt][3] = __float_as_uint(q[8 * GP + 4]);
            }
            uint32_t bh[8][2], bl[8][2];
#pragma unroll
            for (int nt = 0; nt < 8; nt++) {
                const float* p = sBh + (wn + nt * 8 + g) * GP + ks * 8 + t;
                const float* q = sBl + (wn + nt * 8 + g) * GP + ks * 8 + t;
                bh[nt][0] = __float_as_uint(p[0]);
                bh[nt][1] = __float_as_uint(p[4]);
                bl[nt][0] = __float_as_uint(q[0]);
                bl[nt][1] = __float_as_uint(q[4]);
            }
#pragma unroll
            for (int mt = 0; mt < 2; mt++)
#pragma unroll
                for (int nt = 0; nt < 8; nt++) {
                    mma_tf32(d[mt][nt], ah[mt][0], ah[mt][1], ah[mt][2], ah[mt][3],
                             bh[nt][0], bh[nt][1]);
                    mma_tf32(d[mt][nt], ah[mt][0], ah[mt][1], ah[mt][2], ah[mt][3],
                             bl[nt][0], bl[nt][1]);
                    mma_tf32(d[mt][nt], al[mt][0], al[mt][1], al[mt][2], al[mt][3],
                             bh[nt][0], bh[nt][1]);
                }
        }
        // NOTE: no trailing __syncthreads — the write-after-read hazard on this
        // buffer is ordered by the top-of-loop __syncthreads of iteration ch+1
        // (the issue that overwrites this buffer happens only after it).
        buf = (buf + 1) % 3;
    }

#pragma unroll
    for (int nt = 0; nt < 8; nt++) {
        int col = n0 + wn + nt * 8 + 2 * t;
        float b0 = bias[col], b1 = bias[col + 1];
#pragma unroll
        for (int mt = 0; mt < 2; mt++) {
            int row = m0 + wm + mt * 16 + g;
            float2 v0 = make_float2(d[mt][nt][0] + b0, d[mt][nt][1] + b1);
            float2 v1 = make_float2(d[mt][nt][2] + b0, d[mt][nt][3] + b1);
            *(float2*)(C + (size_t)row * Nn + col) = v0;
            *(float2*)(C + (size_t)(row + 8) * Nn + col) = v1;
        }
    }
}

// ----------------------------------------------------------------------------
// CPB MLP
// ----------------------------------------------------------------------------
__global__ __launch_bounds__(512) void cpb_kernel(
    const float* __restrict__ table,
    const float* __restrict__ fc1w, const float* __restrict__ fc1b,
    const float* __restrict__ fc2w, const float* __restrict__ fc2b)
{
    __shared__ float sh[CPB_HIDDEN];
    __shared__ float part[16];
    int t = blockIdx.x;
    int tid = threadIdx.x;

    float c0 = table[t * 2 + 0];
    float c1 = table[t * 2 + 1];
    float hv = c0 * fc1w[tid * 2 + 0] + c1 * fc1w[tid * 2 + 1] + fc1b[tid];
    sh[tid] = fmaxf(hv, 0.f);
    __syncthreads();

    int w = tid >> 5, lane = tid & 31;
    int head = w & 7, seg = w >> 3;
    float s = 0.f;
#pragma unroll
    for (int i = 0; i < 8; i++) {
        int j = seg * 256 + i * 32 + lane;
        s += sh[j] * fc2w[head * CPB_HIDDEN + j];
    }
#pragma unroll
    for (int off = 16; off; off >>= 1)
        s += __shfl_xor_sync(0xffffffffu, s, off);
    if (lane == 0) part[w] = s;
    __syncthreads();
    if (tid < 8) g_bias[t * 8 + tid] = part[tid] + part[tid + 8] + fc2b[tid];
}

// ----------------------------------------------------------------------------
// Materialize bias matrix
// ----------------------------------------------------------------------------
__global__ __launch_bounds__(256) void bias_mat_kernel(const int* __restrict__ relidx)
{
    int gid = blockIdx.x * 256 + threadIdx.x;
    int m4 = gid & 255;
    int n  = (gid >> 8) & 1023;
    int h  = gid >> 18;
    int4 idx = *(const int4*)(relidx + (size_t)n * NN + m4 * 4);
    float4 o;
    o.x = g_bias[idx.x * 8 + h];
    o.y = g_bias[idx.y * 8 + h];
    o.z = g_bias[idx.z * 8 + h];
    o.w = g_bias[idx.w * 8 + h];
    *(float4*)(g_biasmat + ((size_t)h * NN + n) * NN + m4 * 4) = o;
}

// ----------------------------------------------------------------------------
// Prep: split qkv per-(b,h); L2-normalize q,k; scale q. (fp32 outputs)
// ----------------------------------------------------------------------------
__global__ __launch_bounds__(256) void prep_kernel(
    const float* __restrict__ temperature,
    const float* __restrict__ query_emb,
    const float* __restrict__ seq_scale)
{
    int gid = blockIdx.x * 8 + (threadIdx.x >> 5);
    int lane = threadIdx.x & 31;
    int m = gid >> 3, h = gid & 7;
    int b = m >> 10, n = m & 1023;

    const float* src = g_qkv + (size_t)m * (3 * CC) + h * HD;
    float q0 = src[lane],           q1 = src[lane + 32];
    float k0 = src[CC + lane],      k1 = src[CC + lane + 32];
    float v0 = src[2 * CC + lane],  v1 = src[2 * CC + lane + 32];

    float sq = q0 * q0 + q1 * q1;
    float sk = k0 * k0 + k1 * k1;
#pragma unroll
    for (int off = 16; off; off >>= 1) {
        sq += __shfl_xor_sync(0xffffffffu, sq, off);
        sk += __shfl_xor_sync(0xffffffffu, sk, off);
    }
    float qinv = 1.f / fmaxf(sqrtf(sq), 1e-12f);
    float kinv = 1.f / fmaxf(sqrtf(sk), 1e-12f);

    float tv = temperature[h];
    float sp = (tv > 20.f) ? tv : log1pf(expf(tv));
    float scale = sp * seq_scale[0];

    size_t dst = ((size_t)(b * 8 + h) * NN + n) * HD;
    g_q[dst + lane]      = (q0 * qinv + query_emb[h * HD + lane]) * scale;
    g_q[dst + lane + 32] = (q1 * qinv + query_emb[h * HD + lane + 32]) * scale;
    g_k[dst + lane]      = k0 * kinv;
    g_k[dst + lane + 32] = k1 * kinv;
    g_v[dst + lane]      = v0;
    g_v[dst + lane + 32] = v1;
}

// ----------------------------------------------------------------------------
// Flash attention, tf32 mma, 128q x 128k tile, 256 threads (8 warps).
// Warp owns 16 q-rows x full 128-key tile. Stage-time hi/lo splits; V uses
// hi-only (2-term PV). PV uses in-register c->a fragment transpose.
// Epilogue writes tf32 hi/lo of output (fused proj-input split).
// smem: Qh/Ql/Kh/Kl pitch 68, Vh pitch 72 -> 176128 B.
// ----------------------------------------------------------------------------
#define QP 68
#define VP 72
#define ATTN_SMEM ((4 * 128 * QP + 128 * VP) * 4)

__global__ __launch_bounds__(256, 1) void attn_kernel()
{
    extern __shared__ float sm[];
    float* sQh = sm;
    float* sQl = sQh + 128 * QP;
    float* sKh = sQl + 128 * QP;
    float* sKl = sKh + 128 * QP;
    float* sVh = sKl + 128 * QP;

    int bh = blockIdx.x;          // 0..63
    int qt = blockIdx.y;          // 0..7
    int h = bh & 7, b = bh >> 3;
    int tid = threadIdx.x;
    int wid = tid >> 5, lane = tid & 31;
    int g = lane >> 2, t = lane & 3;
    int q0g = qt * 128;
    int wrow = wid * 16;
    int sel = t & 1;
    int src0 = (lane & 28) | (t >> 1);
    int src2 = src0 + 2;

    // stage Q tile with split (128 x 64)
    const float* Qg = g_q + ((size_t)bh * NN + q0g) * HD;
#pragma unroll
    for (int it = 0; it < 8; it++) {
        int i = tid + it * 256;
        int row = i >> 4, c4 = (i & 15) << 2;
        float4 v = *(const float4*)(Qg + row * HD + c4);
        float4 hh, ll;
        hh.x = tf32_rna(v.x); ll.x = v.x - hh.x;
        hh.y = tf32_rna(v.y); ll.y = v.y - hh.y;
        hh.z = tf32_rna(v.z); ll.z = v.z - hh.z;
        hh.w = tf32_rna(v.w); ll.w = v.w - hh.w;
        *(float4*)(sQh + row * QP + c4) = hh;
        *(float4*)(sQl + row * QP + c4) = ll;
    }

    float o[8][4];
#pragma unroll
    for (int nt = 0; nt < 8; nt++)
#pragma unroll
        for (int r = 0; r < 4; r++) o[nt][r] = 0.f;
    float mrow0 = -1e30f, mrow1 = -1e30f, lrow0 = 0.f, lrow1 = 0.f;

    const float* bmat = g_biasmat + ((size_t)h * NN + q0g) * NN;

    for (int kt = 0; kt < 8; kt++) {
        __syncthreads();
        size_t koff = ((size_t)bh * NN + kt * 128) * HD;
#pragma unroll
        for (int it = 0; it < 8; it++) {
            int i = tid + it * 256;
            int row = i >> 4, c4 = (i & 15) << 2;
            float4 kv = *(const float4*)(g_k + koff + row * HD + c4);
            float4 vv = *(const float4*)(g_v + koff + row * HD + c4);
            float4 hh, ll;
            hh.x = tf32_rna(kv.x); ll.x = kv.x - hh.x;
            hh.y = tf32_rna(kv.y); ll.y = kv.y - hh.y;
            hh.z = tf32_rna(kv.z); ll.z = kv.z - hh.z;
            hh.w = tf32_rna(kv.w); ll.w = kv.w - hh.w;
            *(float4*)(sKh + row * QP + c4) = hh;
            *(float4*)(sKl + row * QP + c4) = ll;
            float4 vh;
            vh.x = tf32_rna(vv.x);
            vh.y = tf32_rna(vv.y);
            vh.z = tf32_rna(vv.z);
            vh.w = tf32_rna(vv.w);
            *(float4*)(sVh + row * VP + c4) = vh;
        }
        __syncthreads();

        // ---- QK^T: c[16][4] over all 128 keys (zero splits in loop) ----
        float c[16][4];
#pragma unroll
        for (int nt = 0; nt < 16; nt++)
#pragma unroll
            for (int r = 0; r < 4; r++) c[nt][r] = 0.f;

#pragma unroll
        for (int ks = 0; ks < 8; ks++) {
            const float* ph = sQh + (wrow + g) * QP + ks * 8 + t;
            const float* pl = sQl + (wrow + g) * QP + ks * 8 + t;
            uint32_t ah0 = __float_as_uint(ph[0]);
            uint32_t ah1 = __float_as_uint(ph[8 * QP]);
            uint32_t ah2 = __float_as_uint(ph[4]);
            uint32_t ah3 = __float_as_uint(ph[8 * QP + 4]);
            uint32_t al0 = __float_as_uint(pl[0]);
            uint32_t al1 = __float_as_uint(pl[8 * QP]);
            uint32_t al2 = __float_as_uint(pl[4]);
            uint32_t al3 = __float_as_uint(pl[8 * QP + 4]);
#pragma unroll
            for (int nt = 0; nt < 16; nt++) {
                const float* kh = sKh + (nt * 8 + g) * QP + ks * 8 + t;
                const float* kl = sKl + (nt * 8 + g) * QP + ks * 8 + t;
                uint32_t bh0 = __float_as_uint(kh[0]);
                uint32_t bh1 = __float_as_uint(kh[4]);
                uint32_t bl0 = __float_as_uint(kl[0]);
                uint32_t bl1 = __float_as_uint(kl[4]);
                mma_tf32(c[nt], ah0, ah1, ah2, ah3, bh0, bh1);
                mma_tf32(c[nt], ah0, ah1, ah2, ah3, bl0, bl1);
                mma_tf32(c[nt], al0, al1, al2, al3, bh0, bh1);
            }
        }

        // ---- bias add ----
#pragma unroll
        for (int nt = 0; nt < 16; nt++) {
            const float* bp = bmat + (size_t)(wrow + g) * NN + kt * 128 + nt * 8 + 2 * t;
            float2 b0 = *(const float2*)bp;
            float2 b1 = *(const float2*)(bp + (size_t)8 * NN);
            c[nt][0] += b0.x; c[nt][1] += b0.y;
            c[nt][2] += b1.x; c[nt][3] += b1.y;
        }

        // ---- online softmax (rows g and g+8, in-warp quad reductions) ----
        float mt0 = -1e30f, mt1 = -1e30f;
#pragma unroll
        for (int nt = 0; nt < 16; nt++) {
            mt0 = fmaxf(mt0, fmaxf(c[nt][0], c[nt][1]));
            mt1 = fmaxf(mt1, fmaxf(c[nt][2], c[nt][3]));
        }
        mt0 = fmaxf(mt0, __shfl_xor_sync(0xffffffffu, mt0, 1));
        mt0 = fmaxf(mt0, __shfl_xor_sync(0xffffffffu, mt0, 2));
        mt1 = fmaxf(mt1, __shfl_xor_sync(0xffffffffu, mt1, 1));
        mt1 = fmaxf(mt1, __shfl_xor_sync(0xffffffffu, mt1, 2));

        float nm0 = fmaxf(mrow0, mt0), nm1 = fmaxf(mrow1, mt1);
        float corr0 = __expf(mrow0 - nm0), corr1 = __expf(mrow1 - nm1);
        mrow0 = nm0; mrow1 = nm1;

        float ps0 = 0.f, ps1 = 0.f;
#pragma unroll
        for (int nt = 0; nt < 16; nt++) {
            c[nt][0] = __expf(c[nt][0] - nm0); ps0 += c[nt][0];
            c[nt][1] = __expf(c[nt][1] - nm0); ps0 += c[nt][1];
            c[nt][2] = __expf(c[nt][2] - nm1); ps1 += c[nt][2];
            c[nt][3] = __expf(c[nt][3] - nm1); ps1 += c[nt][3];
        }
        ps0 += __shfl_xor_sync(0xffffffffu, ps0, 1);
        ps0 += __shfl_xor_sync(0xffffffffu, ps0, 2);
        ps1 += __shfl_xor_sync(0xffffffffu, ps1, 1);
        ps1 += __shfl_xor_sync(0xffffffffu, ps1, 2);
        lrow0 = lrow0 * corr0 + ps0;
        lrow1 = lrow1 * corr1 + ps1;

#pragma unroll
        for (int nt = 0; nt < 8; nt++) {
            o[nt][0] *= corr0; o[nt][1] *= corr0;
            o[nt][2] *= corr1; o[nt][3] *= corr1;
        }

        // ---- PV: c-frag -> a-frag via quad shuffles; split P; V hi-only ----
#pragma unroll
        for (int kk = 0; kk < 16; kk++) {
            float y00 = __shfl_sync(0xffffffffu, c[kk][0], src0);
            float y01 = __shfl_sync(0xffffffffu, c[kk][1], src0);
            float y20 = __shfl_sync(0xffffffffu, c[kk][0], src2);
            float y21 = __shfl_sync(0xffffffffu, c[kk][1], src2);
            float y10 = __shfl_sync(0xffffffffu, c[kk][2], src0);
            float y11 = __shfl_sync(0xffffffffu, c[kk][3], src0);
            float y30 = __shfl_sync(0xffffffffu, c[kk][2], src2);
            float y31 = __shfl_sync(0xffffffffu, c[kk][3], src2);
            float p0 = sel ? y01 : y00;
            float p1 = sel ? y11 : y10;
            float p2 = sel ? y21 : y20;
            float p3 = sel ? y31 : y30;
            uint32_t ph0, ph1, ph2, ph3, pl0, pl1, pl2, pl3;
            split2(p0, ph0, pl0); split2(p1, ph1, pl1);
            split2(p2, ph2, pl2); split2(p3, ph3, pl3);
#pragma unroll
            for (int nt = 0; nt < 8; nt++) {
                const float* vh = sVh + (kk * 8 + t) * VP + nt * 8 + g;
                uint32_t vh0 = __float_as_uint(vh[0]);
                uint32_t vh1 = __float_as_uint(vh[4 * VP]);
                mma_tf32(o[nt], ph0, ph1, ph2, ph3, vh0, vh1);
                mma_tf32(o[nt], pl0, pl1, pl2, pl3, vh0, vh1);
            }
        }
    }

    // ---- epilogue: normalize, fused tf32 split of proj input ----
    float inv0 = 1.f / lrow0, inv1 = 1.f / lrow1;
    int rowA = q0g + wrow + g;
#pragma unroll
    for (int nt = 0; nt < 8; nt++) {
        float v0 = o[nt][0] * inv0, v1 = o[nt][1] * inv0;
        float v2 = o[nt][2] * inv1, v3 = o[nt][3] * inv1;
        float h0 = tf32_rna(v0), h1 = tf32_rna(v1);
        float h2 = tf32_rna(v2), h3 = tf32_rna(v3);
        size_t pA = ((size_t)b * NN + rowA) * CC + h * HD + nt * 8 + 2 * t;
        size_t pB = ((size_t)b * NN + rowA + 8) * CC + h * HD + nt * 8 + 2 * t;
        *(float2*)(g_ahi + pA) = make_float2(h0, h1);
        *(float2*)(g_alo + pA) = make_float2(v0 - h0, v1 - h1);
        *(float2*)(g_ahi + pB) = make_float2(h2, h3);
        *(float2*)(g_alo + pB) = make_float2(v2 - h2, v3 - h3);
    }
}

// ----------------------------------------------------------------------------
// launch
// ----------------------------------------------------------------------------
extern "C" void kernel_launch(void* const* d_in, const int* in_sizes, int n_in,
                              void* d_out, int out_size)
{
    int ri = 1;
    while (ri < n_in && in_sizes[ri] != NN * NN) ri++;

    const float* x        = (const float*)d_in[0];
    const int*   relidx   = (const int*)d_in[ri];
    const float* table    = (const float*)d_in[ri + 1];
    const float* seqscale = (const float*)d_in[ri + 2];
    const float* qkv_w    = (const float*)d_in[ri + 3];
    const float* qkv_b    = (const float*)d_in[ri + 4];
    const float* proj_w   = (const float*)d_in[ri + 5];
    const float* proj_b   = (const float*)d_in[ri + 6];
    const float* temp     = (const float*)d_in[ri + 7];
    const float* qemb     = (const float*)d_in[ri + 8];
    const float* fc1w     = (const float*)d_in[ri + 9];
    const float* fc1b     = (const float*)d_in[ri + 10];
    const float* fc2w     = (const float*)d_in[ri + 11];
    const float* fc2b     = (const float*)d_in[ri + 12];
    float* out = (float*)d_out;

    float *qkvbuf, *ahi, *alo, *whi, *wlo, *pwhi, *pwlo;
    cudaGetSymbolAddress((void**)&qkvbuf, g_qkv);
    cudaGetSymbolAddress((void**)&ahi, g_ahi);
    cudaGetSymbolAddress((void**)&alo, g_alo);
    cudaGetSymbolAddress((void**)&whi, g_whi);
    cudaGetSymbolAddress((void**)&wlo, g_wlo);
    cudaGetSymbolAddress((void**)&pwhi, g_pwhi);
    cudaGetSymbolAddress((void**)&pwlo, g_pwlo);

    cudaFuncSetAttribute(mma_gemm_kernel,
                         cudaFuncAttributeMaxDynamicSharedMemorySize, GEMM_SMEM);

    // 1) QKV projection (tf32 mma, 3x split, cp.async 3-stage pipeline)
    split_kernel<<<(M_ROWS * CC / 4 + 255) / 256, 256>>>(x, ahi, alo, M_ROWS * CC / 4);
    split_kernel<<<(3 * CC * CC / 4 + 255) / 256, 256>>>(qkv_w, whi, wlo, 3 * CC * CC / 4);
    {
        dim3 grid(3 * CC / 128, M_ROWS / 128);
        mma_gemm_kernel<<<grid, 256, GEMM_SMEM>>>(ahi, alo, whi, wlo,
                                                  qkv_b, qkvbuf, 3 * CC);
    }

    // 2) CPB MLP -> bias table, then materialize full bias matrix
    cpb_kernel<<<T_ROWS, 512>>>(table, fc1w, fc1b, fc2w, fc2b);
    bias_mat_kernel<<<HEADS * NN * (NN / 4) / 256, 256>>>(relidx);

    // 3) normalize/scale, re-layout (fp32); proj weight split hoisted off tail
    prep_kernel<<<M_ROWS * HEADS / 8, 256>>>(temp, qemb, seqscale);
    split_kernel<<<(CC * CC / 4 + 255) / 256, 256>>>(proj_w, pwhi, pwlo, CC * CC / 4);

    // 4) flash attention (tf32 mma, R11 topology, fused output split)
    {
        cudaFuncSetAttribute(attn_kernel,
                             cudaFuncAttributeMaxDynamicSharedMemorySize,
                             ATTN_SMEM);
        dim3 grid(BB * HEADS, NN / 128);
        attn_kernel<<<grid, 256, ATTN_SMEM>>>();
    }

    // 5) output projection (tf32 mma; input split fused into attn epilogue)
    {
        dim3 grid(CC / 128, M_ROWS / 128);
        mma_gemm_kernel<<<grid, 256, GEMM_SMEM>>>(ahi, alo, pwhi, pwlo,
                                                  proj_b, out, CC);
    }
}

// round 16
// speedup vs baseline: 1.0910x; 1.0295x over previous
#include <cuda_runtime.h>
#include <cuda_fp16.h>
#include <math.h>
#include <stdint.h>

// Problem constants
#define BB 8
#define NN 1024
#define CC 512
#define HEADS 8
#define HD 64
#define T_ROWS 3969
#define M_ROWS (BB * NN)      // 8192
#define CPB_HIDDEN 512

// ----------------------------------------------------------------------------
// Scratch (static device globals; no runtime allocation)
// ----------------------------------------------------------------------------
__device__ float g_qkv[(size_t)M_ROWS * 3 * CC];
__device__ float g_q[(size_t)BB * HEADS * NN * HD];
__device__ float g_k[(size_t)BB * HEADS * NN * HD];
__device__ float g_v[(size_t)BB * HEADS * NN * HD];
__device__ float g_bias[T_ROWS * HEADS];
__device__ __half g_biasmat[(size_t)HEADS * NN * NN];   // fp16 bias matrix
// tf32 split buffers for GEMMs
__device__ float g_ahi[(size_t)M_ROWS * CC];
__device__ float g_alo[(size_t)M_ROWS * CC];
__device__ float g_whi[(size_t)3 * CC * CC];
__device__ float g_wlo[(size_t)3 * CC * CC];
__device__ float g_pwhi[(size_t)CC * CC];
__device__ float g_pwlo[(size_t)CC * CC];

// ----------------------------------------------------------------------------
// tf32 / async helpers
// ----------------------------------------------------------------------------
__device__ __forceinline__ float tf32_rna(float v) {
    uint32_t r;
    asm("cvt.rna.tf32.f32 %0, %1;" : "=r"(r) : "f"(v));
    return __uint_as_float(r);
}

__device__ __forceinline__ void mma_tf32(float* d, uint32_t a0, uint32_t a1,
                                         uint32_t a2, uint32_t a3,
                                         uint32_t b0, uint32_t b1) {
    asm volatile(
        "mma.sync.aligned.m16n8k8.row.col.f32.tf32.tf32.f32 "
        "{%0,%1,%2,%3}, {%4,%5,%6,%7}, {%8,%9}, {%0,%1,%2,%3};"
        : "+f"(d[0]), "+f"(d[1]), "+f"(d[2]), "+f"(d[3])
        : "r"(a0), "r"(a1), "r"(a2), "r"(a3), "r"(b0), "r"(b1));
}

__device__ __forceinline__ void split2(float v, uint32_t& hi, uint32_t& lo) {
    float h = tf32_rna(v);
    hi = __float_as_uint(h);
    lo = __float_as_uint(v - h);
}

__device__ __forceinline__ void cp16(uint32_t saddr, const void* g) {
    asm volatile("cp.async.ca.shared.global [%0], [%1], 16;"
                 :: "r"(saddr), "l"(g));
}
#define CP_COMMIT() asm volatile("cp.async.commit_group;" ::: "memory")
#define CP_WAIT1()  asm volatile("cp.async.wait_group 1;" ::: "memory")

// ----------------------------------------------------------------------------
// Split a float array into tf32 hi/lo parts
// ----------------------------------------------------------------------------
__global__ __launch_bounds__(256) void split_kernel(
    const float* __restrict__ src, float* __restrict__ hi,
    float* __restrict__ lo, int n4)
{
    int i = blockIdx.x * 256 + threadIdx.x;
    if (i >= n4) return;
    float4 v = *(const float4*)(src + i * 4);
    float4 h, l;
    h.x = tf32_rna(v.x); l.x = v.x - h.x;
    h.y = tf32_rna(v.y); l.y = v.y - h.y;
    h.z = tf32_rna(v.z); l.z = v.z - h.z;
    h.w = tf32_rna(v.w); l.w = v.w - h.w;
    *(float4*)(hi + i * 4) = h;
    *(float4*)(lo + i * 4) = l;
}

// ----------------------------------------------------------------------------
// tf32 mma GEMM, cp.async 3-stage pipelined.
// C[M,Nn] = A[M,512] @ W[Nn,512]^T + bias[Nn]. CTA 128x128, BK=32.
// 3-term (AhiBhi+AhiBlo+AloBhi) when n0 < n3lim, else 2-term (drops AloBhi).
// ----------------------------------------------------------------------------
#define GP 36
#define GEMM_STAGE (4 * 128 * GP)          // floats per stage
#define GEMM_SMEM (3 * GEMM_STAGE * 4)     // 221184 B

__global__ __launch_bounds__(256, 1)
void mma_gemm_kernel(const float* __restrict__ Ahi, const float* __restrict__ Alo,
                     const float* __restrict__ Bhi, const float* __restrict__ Blo,
                     const float* __restrict__ bias, float* __restrict__ C,
                     int Nn, int n3lim)
{
    extern __shared__ float sm[];

    int tid = threadIdx.x;
    int wid = tid >> 5, lane = tid & 31;
    int g = lane >> 2, t = lane & 3;
    int wm = (wid & 3) * 32;
    int wn = (wid >> 2) * 64;
    int m0 = blockIdx.y * 128, n0 = blockIdx.x * 128;
    bool full3 = (n0 < n3lim);

    int sm_m[4], sm_k4[4];
    size_t ga[4], gb[4];
#pragma unroll
    for (int it = 0; it < 4; it++) {
        int idx = tid + it * 256;
        sm_m[it] = idx >> 3;
        sm_k4[it] = (idx & 7) << 2;
        ga[it] = (size_t)(m0 + sm_m[it]) * 512 + sm_k4[it];
        gb[it] = (size_t)(n0 + sm_m[it]) * 512 + sm_k4[it];
    }

    uint32_t sbase = (uint32_t)__cvta_generic_to_shared(sm);

    auto issue = [&](int ch, int buf) {
        uint32_t st = sbase + (uint32_t)buf * GEMM_STAGE * 4;
#pragma unroll
        for (int it = 0; it < 4; it++) {
            uint32_t off = (uint32_t)(sm_m[it] * GP + sm_k4[it]) * 4;
            size_t go = ga[it] + ch * 32;
            size_t bo = gb[it] + ch * 32;
            cp16(st + off,                      Ahi + go);
            if (full3)
                cp16(st + 128 * GP * 4 + off,   Alo + go);
            cp16(st + 2 * 128 * GP * 4 + off,   Bhi + bo);
            cp16(st + 3 * 128 * GP * 4 + off,   Blo + bo);
        }
        CP_COMMIT();
    };

    float d[2][8][4];
#pragma unroll
    for (int mt = 0; mt < 2; mt++)
#pragma unroll
        for (int nt = 0; nt < 8; nt++)
#pragma unroll
            for (int r = 0; r < 4; r++) d[mt][nt][r] = 0.f;

    issue(0, 0);
    issue(1, 1);

    int buf = 0;
    for (int ch = 0; ch < 16; ch++) {
        CP_WAIT1();
        __syncthreads();
        if (ch < 14) issue(ch + 2, (buf + 2) % 3);

        float* st = sm + buf * GEMM_STAGE;
        float* sAh = st;
        float* sAl = st + 128 * GP;
        float* sBh = st + 2 * 128 * GP;
        float* sBl = st + 3 * 128 * GP;

#pragma unroll
        for (int ks = 0; ks < 4; ks++) {
            uint32_t ah[2][4], al[2][4];
#pragma unroll
            for (int mt = 0; mt < 2; mt++) {
                const float* p = sAh + (wm + mt * 16 + g) * GP + ks * 8 + t;
                ah[mt][0] = __float_as_uint(p[0]);
                ah[mt][1] = __float_as_uint(p[8 * GP]);
                ah[mt][2] = __float_as_uint(p[4]);
                ah[mt][3] = __float_as_uint(p[8 * GP + 4]);
                if (full3) {
                    const float* q = sAl + (wm + mt * 16 + g) * GP + ks * 8 + t;
                    al[mt][0] = __float_as_uint(q[0]);
                    al[mt][1] = __float_as_uint(q[8 * GP]);
                    al[mt][2] = __float_as_uint(q[4]);
                    al[mt][3] = __float_as_uint(q[8 * GP + 4]);
                }
            }
            uint32_t bh[8][2], bl[8][2];
#pragma unroll
            for (int nt = 0; nt < 8; nt++) {
                const float* p = sBh + (wn + nt * 8 + g) * GP + ks * 8 + t;
                const float* q = sBl + (wn + nt * 8 + g) * GP + ks * 8 + t;
                bh[nt][0] = __float_as_uint(p[0]);
                bh[nt][1] = __float_as_uint(p[4]);
                bl[nt][0] = __float_as_uint(q[0]);
                bl[nt][1] = __float_as_uint(q[4]);
            }
#pragma unroll
            for (int mt = 0; mt < 2; mt++)
#pragma unroll
                for (int nt = 0; nt < 8; nt++) {
                    mma_tf32(d[mt][nt], ah[mt][0], ah[mt][1], ah[mt][2], ah[mt][3],
                             bh[nt][0], bh[nt][1]);
                    mma_tf32(d[mt][nt], ah[mt][0], ah[mt][1], ah[mt][2], ah[mt][3],
                             bl[nt][0], bl[nt][1]);
                    if (full3)
                        mma_tf32(d[mt][nt], al[mt][0], al[mt][1], al[mt][2], al[mt][3],
                                 bh[nt][0], bh[nt][1]);
                }
        }
        buf = (buf + 1) % 3;
    }

#pragma unroll
    for (int nt = 0; nt < 8; nt++) {
        int col = n0 + wn + nt * 8 + 2 * t;
        float b0 = bias[col], b1 = bias[col + 1];
#pragma unroll
        for (int mt = 0; mt < 2; mt++) {
            int row = m0 + wm + mt * 16 + g;
            float2 v0 = make_float2(d[mt][nt][0] + b0, d[mt][nt][1] + b1);
            float2 v1 = make_float2(d[mt][nt][2] + b0, d[mt][nt][3] + b1);
            *(float2*)(C + (size_t)row * Nn + col) = v0;
            *(float2*)(C + (size_t)(row + 8) * Nn + col) = v1;
        }
    }
}

// ----------------------------------------------------------------------------
// CPB MLP
// ----------------------------------------------------------------------------
__global__ __launch_bounds__(512) void cpb_kernel(
    const float* __restrict__ table,
    const float* __restrict__ fc1w, const float* __restrict__ fc1b,
    const float* __restrict__ fc2w, const float* __restrict__ fc2b)
{
    __shared__ float sh[CPB_HIDDEN];
    __shared__ float part[16];
    int t = blockIdx.x;
    int tid = threadIdx.x;

    float c0 = table[t * 2 + 0];
    float c1 = table[t * 2 + 1];
    float hv = c0 * fc1w[tid * 2 + 0] + c1 * fc1w[tid * 2 + 1] + fc1b[tid];
    sh[tid] = fmaxf(hv, 0.f);
    __syncthreads();

    int w = tid >> 5, lane = tid & 31;
    int head = w & 7, seg = w >> 3;
    float s = 0.f;
#pragma unroll
    for (int i = 0; i < 8; i++) {
        int j = seg * 256 + i * 32 + lane;
        s += sh[j] * fc2w[head * CPB_HIDDEN + j];
    }
#pragma unroll
    for (int off = 16; off; off >>= 1)
        s += __shfl_xor_sync(0xffffffffu, s, off);
    if (lane == 0) part[w] = s;
    __syncthreads();
    if (tid < 8) g_bias[t * 8 + tid] = part[tid] + part[tid + 8] + fc2b[tid];
}

// ----------------------------------------------------------------------------
// Materialize bias matrix (fp16)
// ----------------------------------------------------------------------------
__global__ __launch_bounds__(256) void bias_mat_kernel(const int* __restrict__ relidx)
{
    int gid = blockIdx.x * 256 + threadIdx.x;
    int m4 = gid & 255;
    int n  = (gid >> 8) & 1023;
    int h  = gid >> 18;
    int4 idx = *(const int4*)(relidx + (size_t)n * NN + m4 * 4);
    union { __half2 h2[2]; uint2 u; } pk;
    pk.h2[0] = __floats2half2_rn(g_bias[idx.x * 8 + h], g_bias[idx.y * 8 + h]);
    pk.h2[1] = __floats2half2_rn(g_bias[idx.z * 8 + h], g_bias[idx.w * 8 + h]);
    *(uint2*)(g_biasmat + ((size_t)h * NN + n) * NN + m4 * 4) = pk.u;
}

// ----------------------------------------------------------------------------
// Prep: split qkv per-(b,h); L2-normalize q,k; scale q. (fp32 outputs)
// ----------------------------------------------------------------------------
__global__ __launch_bounds__(256) void prep_kernel(
    const float* __restrict__ temperature,
    const float* __restrict__ query_emb,
    const float* __restrict__ seq_scale)
{
    int gid = blockIdx.x * 8 + (threadIdx.x >> 5);
    int lane = threadIdx.x & 31;
    int m = gid >> 3, h = gid & 7;
    int b = m >> 10, n = m & 1023;

    const float* src = g_qkv + (size_t)m * (3 * CC) + h * HD;
    float q0 = src[lane],           q1 = src[lane + 32];
    float k0 = src[CC + lane],      k1 = src[CC + lane + 32];
    float v0 = src[2 * CC + lane],  v1 = src[2 * CC + lane + 32];

    float sq = q0 * q0 + q1 * q1;
    float sk = k0 * k0 + k1 * k1;
#pragma unroll
    for (int off = 16; off; off >>= 1) {
        sq += __shfl_xor_sync(0xffffffffu, sq, off);
        sk += __shfl_xor_sync(0xffffffffu, sk, off);
    }
    float qinv = 1.f / fmaxf(sqrtf(sq), 1e-12f);
    float kinv = 1.f / fmaxf(sqrtf(sk), 1e-12f);

    float tv = temperature[h];
    float sp = (tv > 20.f) ? tv : log1pf(expf(tv));
    float scale = sp * seq_scale[0];

    size_t dst = ((size_t)(b * 8 + h) * NN + n) * HD;
    g_q[dst + lane]      = (q0 * qinv + query_emb[h * HD + lane]) * scale;
    g_q[dst + lane + 32] = (q1 * qinv + query_emb[h * HD + lane + 32]) * scale;
    g_k[dst + lane]      = k0 * kinv;
    g_k[dst + lane + 32] = k1 * kinv;
    g_v[dst + lane]      = v0;
    g_v[dst + lane + 32] = v1;
}

// ----------------------------------------------------------------------------
// Flash attention, tf32 mma, 128q x 128k tile, 256 threads (8 warps).
// R11 topology. Stage-time hi/lo splits; V hi-only PV (2-term);
// in-register c->a fragment transpose. fp16 bias matrix reads.
// Epilogue writes tf32-rounded output to g_ahi only (proj is 2-term).
// smem: Qh/Ql/Kh/Kl pitch 68, Vh pitch 72 -> 176128 B.
// ----------------------------------------------------------------------------
#define QP 68
#define VP 72
#define ATTN_SMEM ((4 * 128 * QP + 128 * VP) * 4)

__global__ __launch_bounds__(256, 1) void attn_kernel()
{
    extern __shared__ float sm[];
    float* sQh = sm;
    float* sQl = sQh + 128 * QP;
    float* sKh = sQl + 128 * QP;
    float* sKl = sKh + 128 * QP;
    float* sVh = sKl + 128 * QP;

    int bh = blockIdx.x;          // 0..63
    int qt = blockIdx.y;          // 0..7
    int h = bh & 7, b = bh >> 3;
    int tid = threadIdx.x;
    int wid = tid >> 5, lane = tid & 31;
    int g = lane >> 2, t = lane & 3;
    int q0g = qt * 128;
    int wrow = wid * 16;
    int sel = t & 1;
    int src0 = (lane & 28) | (t >> 1);
    int src2 = src0 + 2;

    // stage Q tile with split (128 x 64)
    const float* Qg = g_q + ((size_t)bh * NN + q0g) * HD;
#pragma unroll
    for (int it = 0; it < 8; it++) {
        int i = tid + it * 256;
        int row = i >> 4, c4 = (i & 15) << 2;
        float4 v = *(const float4*)(Qg + row * HD + c4);
        float4 hh, ll;
        hh.x = tf32_rna(v.x); ll.x = v.x - hh.x;
        hh.y = tf32_rna(v.y); ll.y = v.y - hh.y;
        hh.z = tf32_rna(v.z); ll.z = v.z - hh.z;
        hh.w = tf32_rna(v.w); ll.w = v.w - hh.w;
        *(float4*)(sQh + row * QP + c4) = hh;
        *(float4*)(sQl + row * QP + c4) = ll;
    }

    float o[8][4];
#pragma unroll
    for (int nt = 0; nt < 8; nt++)
#pragma unroll
        for (int r = 0; r < 4; r++) o[nt][r] = 0.f;
    float mrow0 = -1e30f, mrow1 = -1e30f, lrow0 = 0.f, lrow1 = 0.f;

    const __half* bmat = g_biasmat + ((size_t)h * NN + q0g) * NN;

    for (int kt = 0; kt < 8; kt++) {
        __syncthreads();
        size_t koff = ((size_t)bh * NN + kt * 128) * HD;
#pragma unroll
        for (int it = 0; it < 8; it++) {
            int i = tid + it * 256;
            int row = i >> 4, c4 = (i & 15) << 2;
            float4 kv = *(const float4*)(g_k + koff + row * HD + c4);
            float4 vv = *(const float4*)(g_v + koff + row * HD + c4);
            float4 hh, ll;
            hh.x = tf32_rna(kv.x); ll.x = kv.x - hh.x;
            hh.y = tf32_rna(kv.y); ll.y = kv.y - hh.y;
            hh.z = tf32_rna(kv.z); ll.z = kv.z - hh.z;
            hh.w = tf32_rna(kv.w); ll.w = kv.w - hh.w;
            *(float4*)(sKh + row * QP + c4) = hh;
            *(float4*)(sKl + row * QP + c4) = ll;
            float4 vh;
            vh.x = tf32_rna(vv.x);
            vh.y = tf32_rna(vv.y);
            vh.z = tf32_rna(vv.z);
            vh.w = tf32_rna(vv.w);
            *(float4*)(sVh + row * VP + c4) = vh;
        }
        __syncthreads();

        // ---- QK^T: c[16][4] over all 128 keys ----
        float c[16][4];
#pragma unroll
        for (int nt = 0; nt < 16; nt++)
#pragma unroll
            for (int r = 0; r < 4; r++) c[nt][r] = 0.f;

#pragma unroll
        for (int ks = 0; ks < 8; ks++) {
            const float* ph = sQh + (wrow + g) * QP + ks * 8 + t;
            const float* pl = sQl + (wrow + g) * QP + ks * 8 + t;
            uint32_t ah0 = __float_as_uint(ph[0]);
            uint32_t ah1 = __float_as_uint(ph[8 * QP]);
            uint32_t ah2 = __float_as_uint(ph[4]);
            uint32_t ah3 = __float_as_uint(ph[8 * QP + 4]);
            uint32_t al0 = __float_as_uint(pl[0]);
            uint32_t al1 = __float_as_uint(pl[8 * QP]);
            uint32_t al2 = __float_as_uint(pl[4]);
            uint32_t al3 = __float_as_uint(pl[8 * QP + 4]);
#pragma unroll
            for (int nt = 0; nt < 16; nt++) {
                const float* kh = sKh + (nt * 8 + g) * QP + ks * 8 + t;
                const float* kl = sKl + (nt * 8 + g) * QP + ks * 8 + t;
                uint32_t bh0 = __float_as_uint(kh[0]);
                uint32_t bh1 = __float_as_uint(kh[4]);
                uint32_t bl0 = __float_as_uint(kl[0]);
                uint32_t bl1 = __float_as_uint(kl[4]);
                mma_tf32(c[nt], ah0, ah1, ah2, ah3, bh0, bh1);
                mma_tf32(c[nt], ah0, ah1, ah2, ah3, bl0, bl1);
                mma_tf32(c[nt], al0, al1, al2, al3, bh0, bh1);
            }
        }

        // ---- bias add (fp16 bias matrix) ----
#pragma unroll
        for (int nt = 0; nt < 16; nt++) {
            const __half* bp = bmat + (size_t)(wrow + g) * NN + kt * 128 + nt * 8 + 2 * t;
            float2 b0 = __half22float2(*(const __half2*)bp);
            float2 b1 = __half22float2(*(const __half2*)(bp + (size_t)8 * NN));
            c[nt][0] += b0.x; c[nt][1] += b0.y;
            c[nt][2] += b1.x; c[nt][3] += b1.y;
        }

        // ---- online softmax (rows g and g+8, in-warp quad reductions) ----
        float mt0 = -1e30f, mt1 = -1e30f;
#pragma unroll
        for (int nt = 0; nt < 16; nt++) {
            mt0 = fmaxf(mt0, fmaxf(c[nt][0], c[nt][1]));
            mt1 = fmaxf(mt1, fmaxf(c[nt][2], c[nt][3]));
        }
        mt0 = fmaxf(mt0, __shfl_xor_sync(0xffffffffu, mt0, 1));
        mt0 = fmaxf(mt0, __shfl_xor_sync(0xffffffffu, mt0, 2));
        mt1 = fmaxf(mt1, __shfl_xor_sync(0xffffffffu, mt1, 1));
        mt1 = fmaxf(mt1, __shfl_xor_sync(0xffffffffu, mt1, 2));

        float nm0 = fmaxf(mrow0, mt0), nm1 = fmaxf(mrow1, mt1);
        float corr0 = __expf(mrow0 - nm0), corr1 = __expf(mrow1 - nm1);
        mrow0 = nm0; mrow1 = nm1;

        float ps0 = 0.f, ps1 = 0.f;
#pragma unroll
        for (int nt = 0; nt < 16; nt++) {
            c[nt][0] = __expf(c[nt][0] - nm0); ps0 += c[nt][0];
            c[nt][1] = __expf(c[nt][1] - nm0); ps0 += c[nt][1];
            c[nt][2] = __expf(c[nt][2] - nm1); ps1 += c[nt][2];
            c[nt][3] = __expf(c[nt][3] - nm1); ps1 += c[nt][3];
        }
        ps0 += __shfl_xor_sync(0xffffffffu, ps0, 1);
        ps0 += __shfl_xor_sync(0xffffffffu, ps0, 2);
        ps1 += __shfl_xor_sync(0xffffffffu, ps1, 1);
        ps1 += __shfl_xor_sync(0xffffffffu, ps1, 2);
        lrow0 = lrow0 * corr0 + ps0;
        lrow1 = lrow1 * corr1 + ps1;

#pragma unroll
        for (int nt = 0; nt < 8; nt++) {
            o[nt][0] *= corr0; o[nt][1] *= corr0;
            o[nt][2] *= corr1; o[nt][3] *= corr1;
        }

        // ---- PV: c-frag -> a-frag via quad shuffles; split P; V hi-only ----
#pragma unroll
        for (int kk = 0; kk < 16; kk++) {
            float y00 = __shfl_sync(0xffffffffu, c[kk][0], src0);
            float y01 = __shfl_sync(0xffffffffu, c[kk][1], src0);
            float y20 = __shfl_sync(0xffffffffu, c[kk][0], src2);
            float y21 = __shfl_sync(0xffffffffu, c[kk][1], src2);
            float y10 = __shfl_sync(0xffffffffu, c[kk][2], src0);
            float y11 = __shfl_sync(0xffffffffu, c[kk][3], src0);
            float y30 = __shfl_sync(0xffffffffu, c[kk][2], src2);
            float y31 = __shfl_sync(0xffffffffu, c[kk][3], src2);
            float p0 = sel ? y01 : y00;
            float p1 = sel ? y11 : y10;
            float p2 = sel ? y21 : y20;
            float p3 = sel ? y31 : y30;
            uint32_t ph0, ph1, ph2, ph3, pl0, pl1, pl2, pl3;
            split2(p0, ph0, pl0); split2(p1, ph1, pl1);
            split2(p2, ph2, pl2); split2(p3, ph3, pl3);
#pragma unroll
            for (int nt = 0; nt < 8; nt++) {
                const float* vh = sVh + (kk * 8 + t) * VP + nt * 8 + g;
                uint32_t vh0 = __float_as_uint(vh[0]);
                uint32_t vh1 = __float_as_uint(vh[4 * VP]);
                mma_tf32(o[nt], ph0, ph1, ph2, ph3, vh0, vh1);
                mma_tf32(o[nt], pl0, pl1, pl2, pl3, vh0, vh1);
            }
        }
    }

    // ---- epilogue: normalize, write tf32-rounded proj input (hi only) ----
    float inv0 = 1.f / lrow0, inv1 = 1.f / lrow1;
    int rowA = q0g + wrow + g;
#pragma unroll
    for (int nt = 0; nt < 8; nt++) {
        float v0 = o[nt][0] * inv0, v1 = o[nt][1] * inv0;
        float v2 = o[nt][2] * inv1, v3 = o[nt][3] * inv1;
        size_t pA = ((size_t)b * NN + rowA) * CC + h * HD + nt * 8 + 2 * t;
        size_t pB = ((size_t)b * NN + rowA + 8) * CC + h * HD + nt * 8 + 2 * t;
        *(float2*)(g_ahi + pA) = make_float2(tf32_rna(v0), tf32_rna(v1));
        *(float2*)(g_ahi + pB) = make_float2(tf32_rna(v2), tf32_rna(v3));
    }
}

// ----------------------------------------------------------------------------
// launch
// ----------------------------------------------------------------------------
extern "C" void kernel_launch(void* const* d_in, const int* in_sizes, int n_in,
                              void* d_out, int out_size)
{
    int ri = 1;
    while (ri < n_in && in_sizes[ri] != NN * NN) ri++;

    const float* x        = (const float*)d_in[0];
    const int*   relidx   = (const int*)d_in[ri];
    const float* table    = (const float*)d_in[ri + 1];
    const float* seqscale = (const float*)d_in[ri + 2];
    const float* qkv_w    = (const float*)d_in[ri + 3];
    const float* qkv_b    = (const float*)d_in[ri + 4];
    const float* proj_w   = (const float*)d_in[ri + 5];
    const float* proj_b   = (const float*)d_in[ri + 6];
    const float* temp     = (const float*)d_in[ri + 7];
    const float* qemb     = (const float*)d_in[ri + 8];
    const float* fc1w     = (const float*)d_in[ri + 9];
    const float* fc1b     = (const float*)d_in[ri + 10];
    const float* fc2w     = (const float*)d_in[ri + 11];
    const float* fc2b     = (const float*)d_in[ri + 12];
    float* out = (float*)d_out;

    float *qkvbuf, *ahi, *alo, *whi, *wlo, *pwhi, *pwlo;
    cudaGetSymbolAddress((void**)&qkvbuf, g_qkv);
    cudaGetSymbolAddress((void**)&ahi, g_ahi);
    cudaGetSymbolAddress((void**)&alo, g_alo);
    cudaGetSymbolAddress((void**)&whi, g_whi);
    cudaGetSymbolAddress((void**)&wlo, g_wlo);
    cudaGetSymbolAddress((void**)&pwhi, g_pwhi);
    cudaGetSymbolAddress((void**)&pwlo, g_pwlo);

    cudaFuncSetAttribute(mma_gemm_kernel,
                         cudaFuncAttributeMaxDynamicSharedMemorySize, GEMM_SMEM);

    // 1) QKV projection (3-term for Q/K tiles, 2-term for V tiles)
    split_kernel<<<(M_ROWS * CC / 4 + 255) / 256, 256>>>(x, ahi, alo, M_ROWS * CC / 4);
    split_kernel<<<(3 * CC * CC / 4 + 255) / 256, 256>>>(qkv_w, whi, wlo, 3 * CC * CC / 4);
    {
        dim3 grid(3 * CC / 128, M_ROWS / 128);
        mma_gemm_kernel<<<grid, 256, GEMM_SMEM>>>(ahi, alo, whi, wlo,
                                                  qkv_b, qkvbuf, 3 * CC, 2 * CC);
    }

    // 2) CPB MLP -> bias table, then materialize fp16 bias matrix
    cpb_kernel<<<T_ROWS, 512>>>(table, fc1w, fc1b, fc2w, fc2b);
    bias_mat_kernel<<<HEADS * NN * (NN / 4) / 256, 256>>>(relidx);

    // 3) normalize/scale, re-layout (fp32); proj weight split hoisted off tail
    prep_kernel<<<M_ROWS * HEADS / 8, 256>>>(temp, qemb, seqscale);
    split_kernel<<<(CC * CC / 4 + 255) / 256, 256>>>(proj_w, pwhi, pwlo, CC * CC / 4);

    // 4) flash attention (tf32 mma, R11 topology, fused output rounding)
    {
        cudaFuncSetAttribute(attn_kernel,
                             cudaFuncAttributeMaxDynamicSharedMemorySize,
                             ATTN_SMEM);
        dim3 grid(BB * HEADS, NN / 128);
        attn_kernel<<<grid, 256, ATTN_SMEM>>>();
    }

    // 5) output projection (2-term: n3lim = 0)
    {
        dim3 grid(CC / 128, M_ROWS / 128);
        mma_gemm_kernel<<<grid, 256, GEMM_SMEM>>>(ahi, alo, pwhi, pwlo,
                                                  proj_b, out, CC, 0);
    }
}

// round 17
// speedup vs baseline: 1.2118x; 1.1107x over previous
#include <cuda_runtime.h>
#include <cuda_fp16.h>
#include <math.h>
#include <stdint.h>

// Problem constants
#define BB 8
#define NN 1024
#define CC 512
#define HEADS 8
#define HD 64
#define T_ROWS 3969
#define M_ROWS (BB * NN)      // 8192
#define CPB_HIDDEN 512

// ----------------------------------------------------------------------------
// Scratch (static device globals; no runtime allocation)
// ----------------------------------------------------------------------------
__device__ float g_qkv[(size_t)M_ROWS * 3 * CC];
__device__ float g_q[(size_t)BB * HEADS * NN * HD];
__device__ float g_k[(size_t)BB * HEADS * NN * HD];
__device__ float g_v[(size_t)BB * HEADS * NN * HD];
__device__ float g_bias[T_ROWS * HEADS];
__device__ __half g_biasmat[(size_t)HEADS * NN * NN];   // fp16 bias matrix
// tf32 split buffers for GEMMs
__device__ float g_ahi[(size_t)M_ROWS * CC];
__device__ float g_alo[(size_t)M_ROWS * CC];
__device__ float g_whi[(size_t)3 * CC * CC];
__device__ float g_wlo[(size_t)3 * CC * CC];
__device__ float g_pwhi[(size_t)CC * CC];
__device__ float g_pwlo[(size_t)CC * CC];

// ----------------------------------------------------------------------------
// tf32 / fp16 / async helpers
// ----------------------------------------------------------------------------
__device__ __forceinline__ float tf32_rna(float v) {
    uint32_t r;
    asm("cvt.rna.tf32.f32 %0, %1;" : "=r"(r) : "f"(v));
    return __uint_as_float(r);
}

__device__ __forceinline__ void mma_tf32(float* d, uint32_t a0, uint32_t a1,
                                         uint32_t a2, uint32_t a3,
                                         uint32_t b0, uint32_t b1) {
    asm volatile(
        "mma.sync.aligned.m16n8k8.row.col.f32.tf32.tf32.f32 "
        "{%0,%1,%2,%3}, {%4,%5,%6,%7}, {%8,%9}, {%0,%1,%2,%3};"
        : "+f"(d[0]), "+f"(d[1]), "+f"(d[2]), "+f"(d[3])
        : "r"(a0), "r"(a1), "r"(a2), "r"(a3), "r"(b0), "r"(b1));
}

__device__ __forceinline__ void mma_f16(float* d, uint32_t a0, uint32_t a1,
                                        uint32_t a2, uint32_t a3,
                                        uint32_t b0, uint32_t b1) {
    asm volatile(
        "mma.sync.aligned.m16n8k16.row.col.f32.f16.f16.f32 "
        "{%0,%1,%2,%3}, {%4,%5,%6,%7}, {%8,%9}, {%0,%1,%2,%3};"
        : "+f"(d[0]), "+f"(d[1]), "+f"(d[2]), "+f"(d[3])
        : "r"(a0), "r"(a1), "r"(a2), "r"(a3), "r"(b0), "r"(b1));
}

__device__ __forceinline__ uint32_t f2h2(float a, float b) {
    __half2 h = __floats2half2_rn(a, b);
    return *(uint32_t*)&h;
}

__device__ __forceinline__ void cp16(uint32_t saddr, const void* g) {
    asm volatile("cp.async.ca.shared.global [%0], [%1], 16;"
                 :: "r"(saddr), "l"(g));
}
#define CP_COMMIT() asm volatile("cp.async.commit_group;" ::: "memory")
#define CP_WAIT1()  asm volatile("cp.async.wait_group 1;" ::: "memory")

// ----------------------------------------------------------------------------
// Split a float array into tf32 hi/lo parts
// ----------------------------------------------------------------------------
__global__ __launch_bounds__(256) void split_kernel(
    const float* __restrict__ src, float* __restrict__ hi,
    float* __restrict__ lo, int n4)
{
    int i = blockIdx.x * 256 + threadIdx.x;
    if (i >= n4) return;
    float4 v = *(const float4*)(src + i * 4);
    float4 h, l;
    h.x = tf32_rna(v.x); l.x = v.x - h.x;
    h.y = tf32_rna(v.y); l.y = v.y - h.y;
    h.z = tf32_rna(v.z); l.z = v.z - h.z;
    h.w = tf32_rna(v.w); l.w = v.w - h.w;
    *(float4*)(hi + i * 4) = h;
    *(float4*)(lo + i * 4) = l;
}

// ----------------------------------------------------------------------------
// tf32 mma GEMM, cp.async 3-stage pipelined. 3-term for n0 < n3lim else 2-term.
// ----------------------------------------------------------------------------
#define GP 36
#define GEMM_STAGE (4 * 128 * GP)
#define GEMM_SMEM (3 * GEMM_STAGE * 4)

__global__ __launch_bounds__(256, 1)
void mma_gemm_kernel(const float* __restrict__ Ahi, const float* __restrict__ Alo,
                     const float* __restrict__ Bhi, const float* __restrict__ Blo,
                     const float* __restrict__ bias, float* __restrict__ C,
                     int Nn, int n3lim)
{
    extern __shared__ float sm[];

    int tid = threadIdx.x;
    int wid = tid >> 5, lane = tid & 31;
    int g = lane >> 2, t = lane & 3;
    int wm = (wid & 3) * 32;
    int wn = (wid >> 2) * 64;
    int m0 = blockIdx.y * 128, n0 = blockIdx.x * 128;
    bool full3 = (n0 < n3lim);

    int sm_m[4], sm_k4[4];
    size_t ga[4], gb[4];
#pragma unroll
    for (int it = 0; it < 4; it++) {
        int idx = tid + it * 256;
        sm_m[it] = idx >> 3;
        sm_k4[it] = (idx & 7) << 2;
        ga[it] = (size_t)(m0 + sm_m[it]) * 512 + sm_k4[it];
        gb[it] = (size_t)(n0 + sm_m[it]) * 512 + sm_k4[it];
    }

    uint32_t sbase = (uint32_t)__cvta_generic_to_shared(sm);

    auto issue = [&](int ch, int buf) {
        uint32_t st = sbase + (uint32_t)buf * GEMM_STAGE * 4;
#pragma unroll
        for (int it = 0; it < 4; it++) {
            uint32_t off = (uint32_t)(sm_m[it] * GP + sm_k4[it]) * 4;
            size_t go = ga[it] + ch * 32;
            size_t bo = gb[it] + ch * 32;
            cp16(st + off,                      Ahi + go);
            if (full3)
                cp16(st + 128 * GP * 4 + off,   Alo + go);
            cp16(st + 2 * 128 * GP * 4 + off,   Bhi + bo);
            cp16(st + 3 * 128 * GP * 4 + off,   Blo + bo);
        }
        CP_COMMIT();
    };

    float d[2][8][4];
#pragma unroll
    for (int mt = 0; mt < 2; mt++)
#pragma unroll
        for (int nt = 0; nt < 8; nt++)
#pragma unroll
            for (int r = 0; r < 4; r++) d[mt][nt][r] = 0.f;

    issue(0, 0);
    issue(1, 1);

    int buf = 0;
    for (int ch = 0; ch < 16; ch++) {
        CP_WAIT1();
        __syncthreads();
        if (ch < 14) issue(ch + 2, (buf + 2) % 3);

        float* st = sm + buf * GEMM_STAGE;
        float* sAh = st;
        float* sAl = st + 128 * GP;
        float* sBh = st + 2 * 128 * GP;
        float* sBl = st + 3 * 128 * GP;

#pragma unroll
        for (int ks = 0; ks < 4; ks++) {
            uint32_t ah[2][4], al[2][4];
#pragma unroll
            for (int mt = 0; mt < 2; mt++) {
                const float* p = sAh + (wm + mt * 16 + g) * GP + ks * 8 + t;
                ah[mt][0] = __float_as_uint(p[0]);
                ah[mt][1] = __float_as_uint(p[8 * GP]);
                ah[mt][2] = __float_as_uint(p[4]);
                ah[mt][3] = __float_as_uint(p[8 * GP + 4]);
                if (full3) {
                    const float* q = sAl + (wm + mt * 16 + g) * GP + ks * 8 + t;
                    al[mt][0] = __float_as_uint(q[0]);
                    al[mt][1] = __float_as_uint(q[8 * GP]);
                    al[mt][2] = __float_as_uint(q[4]);
                    al[mt][3] = __float_as_uint(q[8 * GP + 4]);
                }
            }
            uint32_t bh[8][2], bl[8][2];
#pragma unroll
            for (int nt = 0; nt < 8; nt++) {
                const float* p = sBh + (wn + nt * 8 + g) * GP + ks * 8 + t;
                const float* q = sBl + (wn + nt * 8 + g) * GP + ks * 8 + t;
                bh[nt][0] = __float_as_uint(p[0]);
                bh[nt][1] = __float_as_uint(p[4]);
                bl[nt][0] = __float_as_uint(q[0]);
                bl[nt][1] = __float_as_uint(q[4]);
            }
#pragma unroll
            for (int mt = 0; mt < 2; mt++)
#pragma unroll
                for (int nt = 0; nt < 8; nt++) {
                    mma_tf32(d[mt][nt], ah[mt][0], ah[mt][1], ah[mt][2], ah[mt][3],
                             bh[nt][0], bh[nt][1]);
                    mma_tf32(d[mt][nt], ah[mt][0], ah[mt][1], ah[mt][2], ah[mt][3],
                             bl[nt][0], bl[nt][1]);
                    if (full3)
                        mma_tf32(d[mt][nt], al[mt][0], al[mt][1], al[mt][2], al[mt][3],
                                 bh[nt][0], bh[nt][1]);
                }
        }
        buf = (buf + 1) % 3;
    }

#pragma unroll
    for (int nt = 0; nt < 8; nt++) {
        int col = n0 + wn + nt * 8 + 2 * t;
        float b0 = bias[col], b1 = bias[col + 1];
#pragma unroll
        for (int mt = 0; mt < 2; mt++) {
            int row = m0 + wm + mt * 16 + g;
            float2 v0 = make_float2(d[mt][nt][0] + b0, d[mt][nt][1] + b1);
            float2 v1 = make_float2(d[mt][nt][2] + b0, d[mt][nt][3] + b1);
            *(float2*)(C + (size_t)row * Nn + col) = v0;
            *(float2*)(C + (size_t)(row + 8) * Nn + col) = v1;
        }
    }
}

// ----------------------------------------------------------------------------
// CPB MLP
// ----------------------------------------------------------------------------
__global__ __launch_bounds__(512) void cpb_kernel(
    const float* __restrict__ table,
    const float* __restrict__ fc1w, const float* __restrict__ fc1b,
    const float* __restrict__ fc2w, const float* __restrict__ fc2b)
{
    __shared__ float sh[CPB_HIDDEN];
    __shared__ float part[16];
    int t = blockIdx.x;
    int tid = threadIdx.x;

    float c0 = table[t * 2 + 0];
    float c1 = table[t * 2 + 1];
    float hv = c0 * fc1w[tid * 2 + 0] + c1 * fc1w[tid * 2 + 1] + fc1b[tid];
    sh[tid] = fmaxf(hv, 0.f);
    __syncthreads();

    int w = tid >> 5, lane = tid & 31;
    int head = w & 7, seg = w >> 3;
    float s = 0.f;
#pragma unroll
    for (int i = 0; i < 8; i++) {
        int j = seg * 256 + i * 32 + lane;
        s += sh[j] * fc2w[head * CPB_HIDDEN + j];
    }
#pragma unroll
    for (int off = 16; off; off >>= 1)
        s += __shfl_xor_sync(0xffffffffu, s, off);
    if (lane == 0) part[w] = s;
    __syncthreads();
    if (tid < 8) g_bias[t * 8 + tid] = part[tid] + part[tid + 8] + fc2b[tid];
}

// ----------------------------------------------------------------------------
// Materialize bias matrix (fp16)
// ----------------------------------------------------------------------------
__global__ __launch_bounds__(256) void bias_mat_kernel(const int* __restrict__ relidx)
{
    int gid = blockIdx.x * 256 + threadIdx.x;
    int m4 = gid & 255;
    int n  = (gid >> 8) & 1023;
    int h  = gid >> 18;
    int4 idx = *(const int4*)(relidx + (size_t)n * NN + m4 * 4);
    union { __half2 h2[2]; uint2 u; } pk;
    pk.h2[0] = __floats2half2_rn(g_bias[idx.x * 8 + h], g_bias[idx.y * 8 + h]);
    pk.h2[1] = __floats2half2_rn(g_bias[idx.z * 8 + h], g_bias[idx.w * 8 + h]);
    *(uint2*)(g_biasmat + ((size_t)h * NN + n) * NN + m4 * 4) = pk.u;
}

// ----------------------------------------------------------------------------
// Prep: split qkv per-(b,h); L2-normalize q,k; scale q. (fp32 outputs)
// ----------------------------------------------------------------------------
__global__ __launch_bounds__(256) void prep_kernel(
    const float* __restrict__ temperature,
    const float* __restrict__ query_emb,
    const float* __restrict__ seq_scale)
{
    int gid = blockIdx.x * 8 + (threadIdx.x >> 5);
    int lane = threadIdx.x & 31;
    int m = gid >> 3, h = gid & 7;
    int b = m >> 10, n = m & 1023;

    const float* src = g_qkv + (size_t)m * (3 * CC) + h * HD;
    float q0 = src[lane],           q1 = src[lane + 32];
    float k0 = src[CC + lane],      k1 = src[CC + lane + 32];
    float v0 = src[2 * CC + lane],  v1 = src[2 * CC + lane + 32];

    float sq = q0 * q0 + q1 * q1;
    float sk = k0 * k0 + k1 * k1;
#pragma unroll
    for (int off = 16; off; off >>= 1) {
        sq += __shfl_xor_sync(0xffffffffu, sq, off);
        sk += __shfl_xor_sync(0xffffffffu, sk, off);
    }
    float qinv = 1.f / fmaxf(sqrtf(sq), 1e-12f);
    float kinv = 1.f / fmaxf(sqrtf(sk), 1e-12f);

    float tv = temperature[h];
    float sp = (tv > 20.f) ? tv : log1pf(expf(tv));
    float scale = sp * seq_scale[0];

    size_t dst = ((size_t)(b * 8 + h) * NN + n) * HD;
    g_q[dst + lane]      = (q0 * qinv + query_emb[h * HD + lane]) * scale;
    g_q[dst + lane + 32] = (q1 * qinv + query_emb[h * HD + lane + 32]) * scale;
    g_k[dst + lane]      = k0 * kinv;
    g_k[dst + lane + 32] = k1 * kinv;
    g_v[dst + lane]      = v0;
    g_v[dst + lane + 32] = v1;
}

// ----------------------------------------------------------------------------
// Flash attention: QK^T in 3-term tf32 mma; PV in fp16 m16n8k16 mma.
// 128q x 128k tile, 256 threads (8 warps), warp owns 16 q-rows.
// c-frag layout == fp16 a-frag layout: P converts via 4 cvt/chunk, no shuffles.
// V staged as half2 key-pairs sVp[64][72] (b-frag reads hit 32 distinct banks).
// fp16 bias matrix reads; epilogue writes tf32-rounded proj input.
// smem: Qh/Ql/Kh/Kl 128x68 f32 + sVp 64x72 half2 -> 157696 B.
// ----------------------------------------------------------------------------
#define QP 68
#define VPP 72
#define ATTN_SMEM ((4 * 128 * QP + 64 * VPP) * 4)

__global__ __launch_bounds__(256, 1) void attn_kernel()
{
    extern __shared__ float sm[];
    float* sQh = sm;
    float* sQl = sQh + 128 * QP;
    float* sKh = sQl + 128 * QP;
    float* sKl = sKh + 128 * QP;
    uint32_t* sVp = (uint32_t*)(sKl + 128 * QP);   // half2(V[2r][d], V[2r+1][d])

    int bh = blockIdx.x;          // 0..63
    int qt = blockIdx.y;          // 0..7
    int h = bh & 7, b = bh >> 3;
    int tid = threadIdx.x;
    int wid = tid >> 5, lane = tid & 31;
    int g = lane >> 2, t = lane & 3;
    int q0g = qt * 128;
    int wrow = wid * 16;

    // stage Q tile with split (128 x 64)
    const float* Qg = g_q + ((size_t)bh * NN + q0g) * HD;
#pragma unroll
    for (int it = 0; it < 8; it++) {
        int i = tid + it * 256;
        int row = i >> 4, c4 = (i & 15) << 2;
        float4 v = *(const float4*)(Qg + row * HD + c4);
        float4 hh, ll;
        hh.x = tf32_rna(v.x); ll.x = v.x - hh.x;
        hh.y = tf32_rna(v.y); ll.y = v.y - hh.y;
        hh.z = tf32_rna(v.z); ll.z = v.z - hh.z;
        hh.w = tf32_rna(v.w); ll.w = v.w - hh.w;
        *(float4*)(sQh + row * QP + c4) = hh;
        *(float4*)(sQl + row * QP + c4) = ll;
    }

    float o[8][4];
#pragma unroll
    for (int nt = 0; nt < 8; nt++)
#pragma unroll
        for (int r = 0; r < 4; r++) o[nt][r] = 0.f;
    float mrow0 = -1e30f, mrow1 = -1e30f, lrow0 = 0.f, lrow1 = 0.f;

    const __half* bmat = g_biasmat + ((size_t)h * NN + q0g) * NN;

    for (int kt = 0; kt < 8; kt++) {
        __syncthreads();
        size_t koff = ((size_t)bh * NN + kt * 128) * HD;
        // K split staging (128 rows x 16 col-groups, 8 iters)
#pragma unroll
        for (int it = 0; it < 8; it++) {
            int i = tid + it * 256;
            int row = i >> 4, c4 = (i & 15) << 2;
            float4 kv = *(const float4*)(g_k + koff + row * HD + c4);
            float4 hh, ll;
            hh.x = tf32_rna(kv.x); ll.x = kv.x - hh.x;
            hh.y = tf32_rna(kv.y); ll.y = kv.y - hh.y;
            hh.z = tf32_rna(kv.z); ll.z = kv.z - hh.z;
            hh.w = tf32_rna(kv.w); ll.w = kv.w - hh.w;
            *(float4*)(sKh + row * QP + c4) = hh;
            *(float4*)(sKl + row * QP + c4) = ll;
        }
        // V fp16 pair staging (64 pair-rows x 16 col-groups, 4 iters)
#pragma unroll
        for (int it = 0; it < 4; it++) {
            int i = tid + it * 256;
            int r = i >> 4, c4 = (i & 15) << 2;
            float4 va = *(const float4*)(g_v + koff + (2 * r) * HD + c4);
            float4 vb = *(const float4*)(g_v + koff + (2 * r + 1) * HD + c4);
            uint4 pk;
            pk.x = f2h2(va.x, vb.x);
            pk.y = f2h2(va.y, vb.y);
            pk.z = f2h2(va.z, vb.z);
            pk.w = f2h2(va.w, vb.w);
            *(uint4*)(sVp + r * VPP + c4) = pk;
        }
        __syncthreads();

        // ---- QK^T: c[16][4] over all 128 keys (3-term tf32) ----
        float c[16][4];
#pragma unroll
        for (int nt = 0; nt < 16; nt++)
#pragma unroll
            for (int r = 0; r < 4; r++) c[nt][r] = 0.f;

#pragma unroll
        for (int ks = 0; ks < 8; ks++) {
            const float* ph = sQh + (wrow + g) * QP + ks * 8 + t;
            const float* pl = sQl + (wrow + g) * QP + ks * 8 + t;
            uint32_t ah0 = __float_as_uint(ph[0]);
            uint32_t ah1 = __float_as_uint(ph[8 * QP]);
            uint32_t ah2 = __float_as_uint(ph[4]);
            uint32_t ah3 = __float_as_uint(ph[8 * QP + 4]);
            uint32_t al0 = __float_as_uint(pl[0]);
            uint32_t al1 = __float_as_uint(pl[8 * QP]);
            uint32_t al2 = __float_as_uint(pl[4]);
            uint32_t al3 = __float_as_uint(pl[8 * QP + 4]);
#pragma unroll
            for (int nt = 0; nt < 16; nt++) {
                const float* kh = sKh + (nt * 8 + g) * QP + ks * 8 + t;
                const float* kl = sKl + (nt * 8 + g) * QP + ks * 8 + t;
                uint32_t bh0 = __float_as_uint(kh[0]);
                uint32_t bh1 = __float_as_uint(kh[4]);
                uint32_t bl0 = __float_as_uint(kl[0]);
                uint32_t bl1 = __float_as_uint(kl[4]);
                mma_tf32(c[nt], ah0, ah1, ah2, ah3, bh0, bh1);
                mma_tf32(c[nt], ah0, ah1, ah2, ah3, bl0, bl1);
                mma_tf32(c[nt], al0, al1, al2, al3, bh0, bh1);
            }
        }

        // ---- bias add (fp16 bias matrix) ----
#pragma unroll
        for (int nt = 0; nt < 16; nt++) {
            const __half* bp = bmat + (size_t)(wrow + g) * NN + kt * 128 + nt * 8 + 2 * t;
            float2 b0 = __half22float2(*(const __half2*)bp);
            float2 b1 = __half22float2(*(const __half2*)(bp + (size_t)8 * NN));
            c[nt][0] += b0.x; c[nt][1] += b0.y;
            c[nt][2] += b1.x; c[nt][3] += b1.y;
        }

        // ---- online softmax (rows g and g+8, in-warp quad reductions) ----
        float mt0 = -1e30f, mt1 = -1e30f;
#pragma unroll
        for (int nt = 0; nt < 16; nt++) {
            mt0 = fmaxf(mt0, fmaxf(c[nt][0], c[nt][1]));
            mt1 = fmaxf(mt1, fmaxf(c[nt][2], c[nt][3]));
        }
        mt0 = fmaxf(mt0, __shfl_xor_sync(0xffffffffu, mt0, 1));
        mt0 = fmaxf(mt0, __shfl_xor_sync(0xffffffffu, mt0, 2));
        mt1 = fmaxf(mt1, __shfl_xor_sync(0xffffffffu, mt1, 1));
        mt1 = fmaxf(mt1, __shfl_xor_sync(0xffffffffu, mt1, 2));

        float nm0 = fmaxf(mrow0, mt0), nm1 = fmaxf(mrow1, mt1);
        float corr0 = __expf(mrow0 - nm0), corr1 = __expf(mrow1 - nm1);
        mrow0 = nm0; mrow1 = nm1;

        float ps0 = 0.f, ps1 = 0.f;
#pragma unroll
        for (int nt = 0; nt < 16; nt++) {
            c[nt][0] = __expf(c[nt][0] - nm0); ps0 += c[nt][0];
            c[nt][1] = __expf(c[nt][1] - nm0); ps0 += c[nt][1];
            c[nt][2] = __expf(c[nt][2] - nm1); ps1 += c[nt][2];
            c[nt][3] = __expf(c[nt][3] - nm1); ps1 += c[nt][3];
        }
        ps0 += __shfl_xor_sync(0xffffffffu, ps0, 1);
        ps0 += __shfl_xor_sync(0xffffffffu, ps0, 2);
        ps1 += __shfl_xor_sync(0xffffffffu, ps1, 1);
        ps1 += __shfl_xor_sync(0xffffffffu, ps1, 2);
        lrow0 = lrow0 * corr0 + ps0;
        lrow1 = lrow1 * corr1 + ps1;

#pragma unroll
        for (int nt = 0; nt < 8; nt++) {
            o[nt][0] *= corr0; o[nt][1] *= corr0;
            o[nt][2] *= corr1; o[nt][3] *= corr1;
        }

        // ---- PV: fp16 m16n8k16. c-frag IS the a-frag layout (no shuffles) ----
#pragma unroll
        for (int j = 0; j < 8; j++) {
            uint32_t a0 = f2h2(c[2 * j][0], c[2 * j][1]);       // row g,   cols 16j+2t..+1
            uint32_t a1 = f2h2(c[2 * j][2], c[2 * j][3]);       // row g+8
            uint32_t a2 = f2h2(c[2 * j + 1][0], c[2 * j + 1][1]); // row g,  cols 16j+8+2t
            uint32_t a3 = f2h2(c[2 * j + 1][2], c[2 * j + 1][3]); // row g+8
            const uint32_t* v0p = sVp + (8 * j + t) * VPP + g;
            const uint32_t* v1p = sVp + (8 * j + t + 4) * VPP + g;
#pragma unroll
            for (int nt = 0; nt < 8; nt++) {
                uint32_t b0 = v0p[nt * 8];   // keys 16j+2t,+1  | dim nt*8+g
                uint32_t b1 = v1p[nt * 8];   // keys 16j+8+2t,+1
                mma_f16(o[nt], a0, a1, a2, a3, b0, b1);
            }
        }
    }

    // ---- epilogue: normalize, write tf32-rounded proj input (hi only) ----
    float inv0 = 1.f / lrow0, inv1 = 1.f / lrow1;
    int rowA = q0g + wrow + g;
#pragma unroll
    for (int nt = 0; nt < 8; nt++) {
        float v0 = o[nt][0] * inv0, v1 = o[nt][1] * inv0;
        float v2 = o[nt][2] * inv1, v3 = o[nt][3] * inv1;
        size_t pA = ((size_t)b * NN + rowA) * CC + h * HD + nt * 8 + 2 * t;
        size_t pB = ((size_t)b * NN + rowA + 8) * CC + h * HD + nt * 8 + 2 * t;
        *(float2*)(g_ahi + pA) = make_float2(tf32_rna(v0), tf32_rna(v1));
        *(float2*)(g_ahi + pB) = make_float2(tf32_rna(v2), tf32_rna(v3));
    }
}

// ----------------------------------------------------------------------------
// launch
// ----------------------------------------------------------------------------
extern "C" void kernel_launch(void* const* d_in, const int* in_sizes, int n_in,
                              void* d_out, int out_size)
{
    int ri = 1;
    while (ri < n_in && in_sizes[ri] != NN * NN) ri++;

    const float* x        = (const float*)d_in[0];
    const int*   relidx   = (const int*)d_in[ri];
    const float* table    = (const float*)d_in[ri + 1];
    const float* seqscale = (const float*)d_in[ri + 2];
    const float* qkv_w    = (const float*)d_in[ri + 3];
    const float* qkv_b    = (const float*)d_in[ri + 4];
    const float* proj_w   = (const float*)d_in[ri + 5];
    const float* proj_b   = (const float*)d_in[ri + 6];
    const float* temp     = (const float*)d_in[ri + 7];
    const float* qemb     = (const float*)d_in[ri + 8];
    const float* fc1w     = (const float*)d_in[ri + 9];
    const float* fc1b     = (const float*)d_in[ri + 10];
    const float* fc2w     = (const float*)d_in[ri + 11];
    const float* fc2b     = (const float*)d_in[ri + 12];
    float* out = (float*)d_out;

    float *qkvbuf, *ahi, *alo, *whi, *wlo, *pwhi, *pwlo;
    cudaGetSymbolAddress((void**)&qkvbuf, g_qkv);
    cudaGetSymbolAddress((void**)&ahi, g_ahi);
    cudaGetSymbolAddress((void**)&alo, g_alo);
    cudaGetSymbolAddress((void**)&whi, g_whi);
    cudaGetSymbolAddress((void**)&wlo, g_wlo);
    cudaGetSymbolAddress((void**)&pwhi, g_pwhi);
    cudaGetSymbolAddress((void**)&pwlo, g_pwlo);

    cudaFuncSetAttribute(mma_gemm_kernel,
                         cudaFuncAttributeMaxDynamicSharedMemorySize, GEMM_SMEM);

    // 1) QKV projection (3-term for Q/K tiles, 2-term for V tiles)
    split_kernel<<<(M_ROWS * CC / 4 + 255) / 256, 256>>>(x, ahi, alo, M_ROWS * CC / 4);
    split_kernel<<<(3 * CC * CC / 4 + 255) / 256, 256>>>(qkv_w, whi, wlo, 3 * CC * CC / 4);
    {
        dim3 grid(3 * CC / 128, M_ROWS / 128);
        mma_gemm_kernel<<<grid, 256, GEMM_SMEM>>>(ahi, alo, whi, wlo,
                                                  qkv_b, qkvbuf, 3 * CC, 2 * CC);
    }

    // 2) CPB MLP -> bias table, then materialize fp16 bias matrix
    cpb_kernel<<<T_ROWS, 512>>>(table, fc1w, fc1b, fc2w, fc2b);
    bias_mat_kernel<<<HEADS * NN * (NN / 4) / 256, 256>>>(relidx);

    // 3) normalize/scale, re-layout (fp32); proj weight split hoisted off tail
    prep_kernel<<<M_ROWS * HEADS / 8, 256>>>(temp, qemb, seqscale);
    split_kernel<<<(CC * CC / 4 + 255) / 256, 256>>>(proj_w, pwhi, pwlo, CC * CC / 4);

    // 4) flash attention (tf32 QK^T + fp16 PV)
    {
        cudaFuncSetAttribute(attn_kernel,
                             cudaFuncAttributeMaxDynamicSharedMemorySize,
                             ATTN_SMEM);
        dim3 grid(BB * HEADS, NN / 128);
        attn_kernel<<<grid, 256, ATTN_SMEM>>>();
    }

    // 5) output projection (2-term: n3lim = 0)
    {
        dim3 grid(CC / 128, M_ROWS / 128);
        mma_gemm_kernel<<<grid, 256, GEMM_SMEM>>>(ahi, alo, pwhi, pwlo,
                                                  proj_b, out, CC, 0);
    }
}